// round 1
// baseline (speedup 1.0000x reference)
#include <cuda_runtime.h>
#include <cuda_bf16.h>
#include <math.h>

#define Bb 16
#define Ff 1024
#define Hh 16
#define Dd 64
#define Ll 8192
#define HD 1024   // H*D

// Output layout (reference return order, flattened as float32):
//   y        [B,F]        at 0
//   kv_key   [B,L,H,D]    at OFF_K
//   kv_value [B,L,H,D]    at OFF_V
//   new_idx  [B]          at OFF_IDX
#define KV_ELEMS ((size_t)Bb * Ll * HD)          // 134217728
#define OFF_Y   ((size_t)0)
#define OFF_K   ((size_t)(Bb * Ff))              // 16384
#define OFF_V   (OFF_K + KV_ELEMS)
#define OFF_IDX (OFF_V + KV_ELEMS)

// Scratch (no allocations allowed -> device globals)
__device__ float g_qkv[3 * Bb * HD];             // q,k,v after reduce
__device__ float g_proj_partial[3 * 8 * Bb * HD];
__device__ float g_attn[Bb * HD];                // attention output (bf16-rounded, stored fp32)
__device__ float g_out_partial[8 * Bb * HD];

static __device__ __forceinline__ float bf16r(float v) {
    return __bfloat162float(__float2bfloat16(v));
}

// ---------------------------------------------------------------------------
// QKV projection partials: 96 blocks = (proj 3) x (out-chunk 4) x (f-chunk 8)
// ---------------------------------------------------------------------------
__global__ void proj_partial_kernel(const float* __restrict__ x,
                                    const float* __restrict__ Wq,
                                    const float* __restrict__ Wk,
                                    const float* __restrict__ Wv) {
    int blk = blockIdx.x;
    int p  = blk >> 5;          // 0..2
    int oc = (blk >> 3) & 3;    // 0..3
    int fc = blk & 7;           // 0..7
    const float* W = (p == 0) ? Wq : (p == 1) ? Wk : Wv;

    __shared__ float xs[Bb][128];
    int tid = threadIdx.x;      // 256 threads
    for (int i = tid; i < Bb * 128; i += 256) {
        int b = i >> 7, f = i & 127;
        xs[b][f] = x[b * Ff + fc * 128 + f];
    }
    __syncthreads();

    int o = oc * 256 + tid;
    float acc[Bb];
#pragma unroll
    for (int b = 0; b < Bb; b++) acc[b] = 0.0f;

    const float* Wp = W + (size_t)(fc * 128) * HD + o;
    for (int f = 0; f < 128; f++) {
        float w = Wp[(size_t)f * HD];
#pragma unroll
        for (int b = 0; b < Bb; b++) acc[b] = fmaf(xs[b][f], w, acc[b]);
    }
#pragma unroll
    for (int b = 0; b < Bb; b++)
        g_proj_partial[((size_t)(p * 8 + fc) * Bb + b) * HD + o] = acc[b];
}

__global__ void proj_reduce_kernel(const float* __restrict__ bq,
                                   const float* __restrict__ bk,
                                   const float* __restrict__ bv) {
    int i = blockIdx.x * blockDim.x + threadIdx.x;   // < 3*B*HD = 49152
    if (i >= 3 * Bb * HD) return;
    int p = i / (Bb * HD);
    int rem = i - p * (Bb * HD);
    int b = rem / HD, o = rem - b * HD;
    float s = ((p == 0) ? bq : (p == 1) ? bk : bv)[o];
#pragma unroll
    for (int c = 0; c < 8; c++)
        s += g_proj_partial[((size_t)(p * 8 + c) * Bb + b) * HD + o];
    g_qkv[i] = s;
}

// ---------------------------------------------------------------------------
// Insert k_new / v_new into the copied caches at row idx % L
// ---------------------------------------------------------------------------
__global__ void insert_kernel(float* __restrict__ out, const int* __restrict__ kv_idx) {
    int b = blockIdx.x >> 1;
    int w = blockIdx.x & 1;          // 0 = key, 1 = value
    int idx = kv_idx[b] % Ll;
    float* dst = out + (w == 0 ? OFF_K : OFF_V) + ((size_t)b * Ll + idx) * HD;
    const float* src = g_qkv + (size_t)(w + 1) * Bb * HD + (size_t)b * HD;
    for (int t = threadIdx.x; t < HD; t += blockDim.x) dst[t] = src[t];
}

// ---------------------------------------------------------------------------
// Decode attention: one block per (b,h); logits resident in smem; two passes.
// Mimics reference precision: q,k,v and probs rounded to bf16, logits/softmax
// fp32, final attn rounded to bf16.
// ---------------------------------------------------------------------------
__global__ __launch_bounds__(256) void attn_kernel(const float* __restrict__ cacheK,
                                                   const float* __restrict__ cacheV,
                                                   const int* __restrict__ kv_idx) {
    int bh = blockIdx.x;
    int b = bh >> 4, h = bh & 15;
    int seq = min(kv_idx[b] + 1, Ll);

    __shared__ float sm_log[Ll];      // 32 KB
    __shared__ float sm_red[48];
    __shared__ float wacc[8][64];     // per-warp V accumulators

    int tid = threadIdx.x, lane = tid & 31, warp = tid >> 5;

    const float* qp = g_qkv + (size_t)b * HD + h * Dd;
    float q0 = bf16r(qp[lane]);
    float q1 = bf16r(qp[lane + 32]);

    const float scale = 0.125f;       // 1/sqrt(64)
    const float* Kb = cacheK + (size_t)b * Ll * HD + h * Dd;

    // Pass 1: logits
    for (int l = warp; l < seq; l += 8) {
        const float* kr = Kb + (size_t)l * HD;
        float k0 = bf16r(kr[lane]);
        float k1 = bf16r(kr[lane + 32]);
        float p = fmaf(q0, k0, q1 * k1);
#pragma unroll
        for (int off = 16; off > 0; off >>= 1)
            p += __shfl_down_sync(0xffffffffu, p, off);
        if (lane == 0) sm_log[l] = p * scale;
    }
    __syncthreads();

    // Block max
    float m = -INFINITY;
    for (int l = tid; l < seq; l += 256) m = fmaxf(m, sm_log[l]);
#pragma unroll
    for (int off = 16; off > 0; off >>= 1)
        m = fmaxf(m, __shfl_down_sync(0xffffffffu, m, off));
    if (lane == 0) sm_red[warp] = m;
    __syncthreads();
    if (tid == 0) {
        float mm = sm_red[0];
#pragma unroll
        for (int w = 1; w < 8; w++) mm = fmaxf(mm, sm_red[w]);
        sm_red[32] = mm;
    }
    __syncthreads();
    m = sm_red[32];

    // exp + sum
    float s = 0.0f;
    for (int l = tid; l < seq; l += 256) {
        float e = expf(sm_log[l] - m);
        sm_log[l] = e;
        s += e;
    }
#pragma unroll
    for (int off = 16; off > 0; off >>= 1)
        s += __shfl_down_sync(0xffffffffu, s, off);
    if (lane == 0) sm_red[warp] = s;
    __syncthreads();
    if (tid == 0) {
        float ss = 0.0f;
#pragma unroll
        for (int w = 0; w < 8; w++) ss += sm_red[w];
        sm_red[33] = ss;
    }
    __syncthreads();
    float inv_s = 1.0f / sm_red[33];

    // Pass 2: probs (bf16) x V (bf16), fp32 accumulate
    float a0 = 0.0f, a1 = 0.0f;
    const float* Vb = cacheV + (size_t)b * Ll * HD + h * Dd;
    for (int l = warp; l < seq; l += 8) {
        const float* vr = Vb + (size_t)l * HD;
        float pb = bf16r(sm_log[l] * inv_s);
        float v0 = bf16r(vr[lane]);
        float v1 = bf16r(vr[lane + 32]);
        a0 = fmaf(pb, v0, a0);
        a1 = fmaf(pb, v1, a1);
    }
    wacc[warp][lane]      = a0;
    __syncthreads();  // reuse wacc in two stages to keep smem small
    // store second half after first half consumed? No: 8x64 holds d=lane only.
    // Handle d+32 via a second smem round.
    if (tid < 64) {
        float t = 0.0f;
#pragma unroll
        for (int w = 0; w < 8; w++) t += wacc[w][tid & 31 ? tid & 31 : tid];
        // placeholder; replaced below
    }
    __syncthreads();
    // -- proper combine: write both halves (wacc is [8][64], reuse fully) --
    wacc[warp][lane]      = a0;
    wacc[warp][lane + 32] = a1;
    __syncthreads();
    if (tid < 64) {
        float t = 0.0f;
#pragma unroll
        for (int w = 0; w < 8; w++) t += wacc[w][tid];
        t = bf16r(t);   // reference attn einsum output dtype is bf16
        g_attn[(size_t)b * HD + h * Dd + tid] = t;
    }
}

// ---------------------------------------------------------------------------
// Output projection: y[b,f] = sum_hd attn[b,hd] * Wo[hd,f] + bo[f]
// ---------------------------------------------------------------------------
__global__ void outproj_partial_kernel(const float* __restrict__ Wo) {
    int fc = blockIdx.x >> 3;   // 0..3
    int hc = blockIdx.x & 7;    // 0..7
    __shared__ float as[Bb][128];
    int tid = threadIdx.x;      // 256
    for (int i = tid; i < Bb * 128; i += 256) {
        int b = i >> 7, j = i & 127;
        as[b][j] = g_attn[(size_t)b * HD + hc * 128 + j];
    }
    __syncthreads();

    int f = fc * 256 + tid;
    float acc[Bb];
#pragma unroll
    for (int b = 0; b < Bb; b++) acc[b] = 0.0f;
    const float* Wp = Wo + (size_t)(hc * 128) * Ff + f;
    for (int j = 0; j < 128; j++) {
        float w = Wp[(size_t)j * Ff];
#pragma unroll
        for (int b = 0; b < Bb; b++) acc[b] = fmaf(as[b][j], w, acc[b]);
    }
#pragma unroll
    for (int b = 0; b < Bb; b++)
        g_out_partial[((size_t)hc * Bb + b) * Ff + f] = acc[b];
}

__global__ void outproj_reduce_kernel(const float* __restrict__ bo,
                                      const int* __restrict__ kv_idx,
                                      float* __restrict__ out) {
    int i = blockIdx.x * blockDim.x + threadIdx.x;   // < B*F = 16384
    if (i < Bb * Ff) {
        int f = i & (Ff - 1);
        float s = bo[f];
#pragma unroll
        for (int c = 0; c < 8; c++)
            s += g_out_partial[(size_t)c * Bb * Ff + i];
        out[OFF_Y + i] = s;
    }
    if (blockIdx.x == 0 && threadIdx.x < Bb) {
        out[OFF_IDX + threadIdx.x] = (float)(kv_idx[threadIdx.x] + 1);
    }
}

// ---------------------------------------------------------------------------
extern "C" void kernel_launch(void* const* d_in, const int* in_sizes, int n_in,
                              void* d_out, int out_size) {
    const float* x    = (const float*)d_in[0];
    const float* kvk  = (const float*)d_in[1];
    const float* kvv  = (const float*)d_in[2];
    const int*   kidx = (const int*)  d_in[3];
    const float* Wq   = (const float*)d_in[4];
    const float* bq   = (const float*)d_in[5];
    const float* Wk   = (const float*)d_in[6];
    const float* bk   = (const float*)d_in[7];
    const float* Wv   = (const float*)d_in[8];
    const float* bv   = (const float*)d_in[9];
    const float* Wo   = (const float*)d_in[10];
    const float* bo   = (const float*)d_in[11];
    float* out = (float*)d_out;

    size_t kv_bytes = KV_ELEMS * sizeof(float);
    // Bulk ring-buffer cache passthrough (dominant cost ~2.1 GB traffic)
    cudaMemcpyAsync(out + OFF_K, kvk, kv_bytes, cudaMemcpyDeviceToDevice);
    cudaMemcpyAsync(out + OFF_V, kvv, kv_bytes, cudaMemcpyDeviceToDevice);

    proj_partial_kernel<<<96, 256>>>(x, Wq, Wk, Wv);
    proj_reduce_kernel<<<48, 1024>>>(bq, bk, bv);
    insert_kernel<<<32, 512>>>(out, kidx);
    attn_kernel<<<Bb * Hh, 256>>>(out + OFF_K, out + OFF_V, kidx);
    outproj_partial_kernel<<<32, 256>>>(Wo);
    outproj_reduce_kernel<<<16, 1024>>>(bo, kidx, out);
}

// round 2
// speedup vs baseline: 2.2079x; 2.2079x over previous
#include <cuda_runtime.h>
#include <cuda_bf16.h>
#include <math.h>

#define Bb 16
#define Ff 1024
#define Hh 16
#define Dd 64
#define Ll 8192
#define HD 1024   // H*D
#define NCH 8     // L-splits for flash-decode
#define CHL (Ll / NCH)   // 1024 rows per chunk

// Output layout (reference return order, flattened as float32):
//   y        [B,F]        at 0
//   kv_key   [B,L,H,D]    at OFF_K
//   kv_value [B,L,H,D]    at OFF_V
//   new_idx  [B]          at OFF_IDX
#define KV_ELEMS ((size_t)Bb * Ll * HD)          // 134217728
#define OFF_Y   ((size_t)0)
#define OFF_K   ((size_t)(Bb * Ff))              // 16384
#define OFF_V   (OFF_K + KV_ELEMS)
#define OFF_IDX (OFF_V + KV_ELEMS)

// Scratch (no allocations allowed -> device globals)
__device__ float g_qkv[3 * Bb * HD];             // q,k,v after reduce
__device__ float g_proj_partial[3 * 8 * Bb * HD];
__device__ float g_logits[(size_t)Bb * Hh * Ll]; // 8 MB
__device__ float g_M[Bb * Hh];
__device__ float g_S[Bb * Hh];
__device__ float g_av_part[Bb * Hh * NCH * Dd];  // 512 KB
__device__ float g_attn[Bb * HD];                // attention output (bf16-rounded fp32)
__device__ float g_out_partial[8 * Bb * HD];

static __device__ __forceinline__ float bf16r(float v) {
    return __bfloat162float(__float2bfloat16(v));
}

// ---------------------------------------------------------------------------
// Bulk cache copy: both K and V, grid-stride float4 (replaces slow memcpy)
// ---------------------------------------------------------------------------
__global__ void copy_kernel(const float4* __restrict__ a,
                            const float4* __restrict__ b,
                            float4* __restrict__ oa,
                            float4* __restrict__ ob) {
    size_t n4 = KV_ELEMS / 4;
    size_t stride = (size_t)gridDim.x * blockDim.x;
    for (size_t i = (size_t)blockIdx.x * blockDim.x + threadIdx.x; i < n4; i += stride) {
        oa[i] = a[i];
        ob[i] = b[i];
    }
}

// ---------------------------------------------------------------------------
// QKV projection partials: 96 blocks = (proj 3) x (out-chunk 4) x (f-chunk 8)
// ---------------------------------------------------------------------------
__global__ void proj_partial_kernel(const float* __restrict__ x,
                                    const float* __restrict__ Wq,
                                    const float* __restrict__ Wk,
                                    const float* __restrict__ Wv) {
    int blk = blockIdx.x;
    int p  = blk >> 5;          // 0..2
    int oc = (blk >> 3) & 3;    // 0..3
    int fc = blk & 7;           // 0..7
    const float* W = (p == 0) ? Wq : (p == 1) ? Wk : Wv;

    __shared__ float xs[Bb][128];
    int tid = threadIdx.x;      // 256 threads
    for (int i = tid; i < Bb * 128; i += 256) {
        int b = i >> 7, f = i & 127;
        xs[b][f] = x[b * Ff + fc * 128 + f];
    }
    __syncthreads();

    int o = oc * 256 + tid;
    float acc[Bb];
#pragma unroll
    for (int b = 0; b < Bb; b++) acc[b] = 0.0f;

    const float* Wp = W + (size_t)(fc * 128) * HD + o;
    for (int f = 0; f < 128; f++) {
        float w = Wp[(size_t)f * HD];
#pragma unroll
        for (int b = 0; b < Bb; b++) acc[b] = fmaf(xs[b][f], w, acc[b]);
    }
#pragma unroll
    for (int b = 0; b < Bb; b++)
        g_proj_partial[((size_t)(p * 8 + fc) * Bb + b) * HD + o] = acc[b];
}

__global__ void proj_reduce_kernel(const float* __restrict__ bq,
                                   const float* __restrict__ bk,
                                   const float* __restrict__ bv) {
    int i = blockIdx.x * blockDim.x + threadIdx.x;   // < 3*B*HD = 49152
    if (i >= 3 * Bb * HD) return;
    int p = i / (Bb * HD);
    int rem = i - p * (Bb * HD);
    int b = rem / HD, o = rem - b * HD;
    float s = ((p == 0) ? bq : (p == 1) ? bk : bv)[o];
#pragma unroll
    for (int c = 0; c < 8; c++)
        s += g_proj_partial[((size_t)(p * 8 + c) * Bb + b) * HD + o];
    g_qkv[i] = s;
}

// ---------------------------------------------------------------------------
// Insert k_new / v_new into the copied caches at row idx % L
// ---------------------------------------------------------------------------
__global__ void insert_kernel(float* __restrict__ out, const int* __restrict__ kv_idx) {
    int b = blockIdx.x >> 1;
    int w = blockIdx.x & 1;          // 0 = key, 1 = value
    int idx = kv_idx[b] % Ll;
    float* dst = out + (w == 0 ? OFF_K : OFF_V) + ((size_t)b * Ll + idx) * HD;
    const float* src = g_qkv + (size_t)(w + 1) * Bb * HD + (size_t)b * HD;
    for (int t = threadIdx.x; t < HD; t += blockDim.x) dst[t] = src[t];
}

// ---------------------------------------------------------------------------
// Flash-decode pass 1: logits per (b,h,chunk). Reads INPUT cache, substituting
// row idx with k_new. bf16 rounding on q and k, fp32 dot (matches reference).
// ---------------------------------------------------------------------------
__global__ __launch_bounds__(256) void logits_kernel(const float* __restrict__ kvk,
                                                     const int* __restrict__ kv_idx) {
    int blk = blockIdx.x;            // b*128 + h*8 + s
    int s = blk & 7;
    int h = (blk >> 3) & 15;
    int b = blk >> 7;
    int seq = min(kv_idx[b] + 1, Ll);
    int l0 = s * CHL;
    if (l0 >= seq) return;
    int lend = min(l0 + CHL, seq);
    int idx = kv_idx[b] % Ll;

    __shared__ float slog[CHL];
    int tid = threadIdx.x, lane = tid & 31, warp = tid >> 5;

    const float* qp = g_qkv + (size_t)b * HD + h * Dd;
    float q0 = bf16r(qp[lane]);
    float q1 = bf16r(qp[lane + 32]);
    const float* Kb = kvk + (size_t)b * Ll * HD + h * Dd;
    const float* knew = g_qkv + (size_t)Bb * HD + (size_t)b * HD + h * Dd;

    for (int l = l0 + warp; l < lend; l += 8) {
        const float* kr = (l == idx) ? knew : (Kb + (size_t)l * HD);
        float k0 = bf16r(kr[lane]);
        float k1 = bf16r(kr[lane + 32]);
        float p = fmaf(q0, k0, q1 * k1);
#pragma unroll
        for (int off = 16; off > 0; off >>= 1)
            p += __shfl_down_sync(0xffffffffu, p, off);
        if (lane == 0) slog[l - l0] = p * 0.125f;   // 1/sqrt(64)
    }
    __syncthreads();

    float* dst = g_logits + ((size_t)(b * Hh + h)) * Ll + l0;
    int n = lend - l0;
    for (int j = tid; j < n; j += 256) dst[j] = slog[j];
}

// ---------------------------------------------------------------------------
// Flash-decode pass 2: global max + sumexp per (b,h) (exact reference math)
// ---------------------------------------------------------------------------
__global__ __launch_bounds__(256) void softmax_stats_kernel(const int* __restrict__ kv_idx) {
    int bh = blockIdx.x;
    int b = bh >> 4;
    int seq = min(kv_idx[b] + 1, Ll);
    const float* lg = g_logits + (size_t)bh * Ll;

    __shared__ float sred[40];
    int tid = threadIdx.x, lane = tid & 31, warp = tid >> 5;

    float m = -INFINITY;
    for (int l = tid; l < seq; l += 256) m = fmaxf(m, lg[l]);
#pragma unroll
    for (int off = 16; off > 0; off >>= 1)
        m = fmaxf(m, __shfl_down_sync(0xffffffffu, m, off));
    if (lane == 0) sred[warp] = m;
    __syncthreads();
    if (tid == 0) {
        float mm = sred[0];
#pragma unroll
        for (int w = 1; w < 8; w++) mm = fmaxf(mm, sred[w]);
        sred[32] = mm;
    }
    __syncthreads();
    m = sred[32];

    float ssum = 0.0f;
    for (int l = tid; l < seq; l += 256) ssum += expf(lg[l] - m);
#pragma unroll
    for (int off = 16; off > 0; off >>= 1)
        ssum += __shfl_down_sync(0xffffffffu, ssum, off);
    if (lane == 0) sred[warp] = ssum;
    __syncthreads();
    if (tid == 0) {
        float st = 0.0f;
#pragma unroll
        for (int w = 0; w < 8; w++) st += sred[w];
        g_M[bh] = m;
        g_S[bh] = st;
    }
}

// ---------------------------------------------------------------------------
// Flash-decode pass 3: prob(bf16) x V(bf16) partials per (b,h,chunk)
// ---------------------------------------------------------------------------
__global__ __launch_bounds__(256) void av_kernel(const float* __restrict__ kvv,
                                                 const int* __restrict__ kv_idx) {
    int blk = blockIdx.x;            // b*128 + h*8 + s
    int s = blk & 7;
    int h = (blk >> 3) & 15;
    int b = blk >> 7;
    int bh = b * Hh + h;
    int seq = min(kv_idx[b] + 1, Ll);
    int l0 = s * CHL;

    int tid = threadIdx.x, lane = tid & 31, warp = tid >> 5;
    float* part = g_av_part + ((size_t)bh * NCH + s) * Dd;

    if (l0 >= seq) {
        if (tid < Dd) part[tid] = 0.0f;
        return;
    }
    int lend = min(l0 + CHL, seq);
    int idx = kv_idx[b] % Ll;

    __shared__ float wacc[8][64];

    float m = g_M[bh];
    float inv_s = 1.0f / g_S[bh];
    const float* lg = g_logits + (size_t)bh * Ll;
    const float* Vb = kvv + (size_t)b * Ll * HD + h * Dd;
    const float* vnew = g_qkv + (size_t)2 * Bb * HD + (size_t)b * HD + h * Dd;

    float a0 = 0.0f, a1 = 0.0f;
    for (int l = l0 + warp; l < lend; l += 8) {
        const float* vr = (l == idx) ? vnew : (Vb + (size_t)l * HD);
        float pb = bf16r(expf(lg[l] - m) * inv_s);
        float v0 = bf16r(vr[lane]);
        float v1 = bf16r(vr[lane + 32]);
        a0 = fmaf(pb, v0, a0);
        a1 = fmaf(pb, v1, a1);
    }
    wacc[warp][lane]      = a0;
    wacc[warp][lane + 32] = a1;
    __syncthreads();
    if (tid < Dd) {
        float t = 0.0f;
#pragma unroll
        for (int w = 0; w < 8; w++) t += wacc[w][tid];
        part[tid] = t;
    }
}

// Combine chunk partials -> attn (bf16-rounded, matches reference dtype)
__global__ void av_reduce_kernel() {
    int i = blockIdx.x * blockDim.x + threadIdx.x;   // < B*HD = 16384
    if (i >= Bb * HD) return;
    int bh = i >> 6;
    int d = i & 63;
    float t = 0.0f;
#pragma unroll
    for (int s = 0; s < NCH; s++)
        t += g_av_part[((size_t)bh * NCH + s) * Dd + d];
    g_attn[i] = bf16r(t);
}

// ---------------------------------------------------------------------------
// Output projection: y[b,f] = sum_hd attn[b,hd] * Wo[hd,f] + bo[f]
// ---------------------------------------------------------------------------
__global__ void outproj_partial_kernel(const float* __restrict__ Wo) {
    int fc = blockIdx.x >> 3;   // 0..3
    int hc = blockIdx.x & 7;    // 0..7
    __shared__ float as[Bb][128];
    int tid = threadIdx.x;      // 256
    for (int i = tid; i < Bb * 128; i += 256) {
        int b = i >> 7, j = i & 127;
        as[b][j] = g_attn[(size_t)b * HD + hc * 128 + j];
    }
    __syncthreads();

    int f = fc * 256 + tid;
    float acc[Bb];
#pragma unroll
    for (int b = 0; b < Bb; b++) acc[b] = 0.0f;
    const float* Wp = Wo + (size_t)(hc * 128) * Ff + f;
    for (int j = 0; j < 128; j++) {
        float w = Wp[(size_t)j * Ff];
#pragma unroll
        for (int b = 0; b < Bb; b++) acc[b] = fmaf(as[b][j], w, acc[b]);
    }
#pragma unroll
    for (int b = 0; b < Bb; b++)
        g_out_partial[((size_t)hc * Bb + b) * Ff + f] = acc[b];
}

__global__ void outproj_reduce_kernel(const float* __restrict__ bo,
                                      const int* __restrict__ kv_idx,
                                      float* __restrict__ out) {
    int i = blockIdx.x * blockDim.x + threadIdx.x;   // < B*F = 16384
    if (i < Bb * Ff) {
        int f = i & (Ff - 1);
        float s = bo[f];
#pragma unroll
        for (int c = 0; c < 8; c++)
            s += g_out_partial[(size_t)c * Bb * Ff + i];
        out[OFF_Y + i] = s;
    }
    if (blockIdx.x == 0 && threadIdx.x < Bb) {
        out[OFF_IDX + threadIdx.x] = (float)(kv_idx[threadIdx.x] + 1);
    }
}

// ---------------------------------------------------------------------------
extern "C" void kernel_launch(void* const* d_in, const int* in_sizes, int n_in,
                              void* d_out, int out_size) {
    const float* x    = (const float*)d_in[0];
    const float* kvk  = (const float*)d_in[1];
    const float* kvv  = (const float*)d_in[2];
    const int*   kidx = (const int*)  d_in[3];
    const float* Wq   = (const float*)d_in[4];
    const float* bq   = (const float*)d_in[5];
    const float* Wk   = (const float*)d_in[6];
    const float* bk   = (const float*)d_in[7];
    const float* Wv   = (const float*)d_in[8];
    const float* bv   = (const float*)d_in[9];
    const float* Wo   = (const float*)d_in[10];
    const float* bo   = (const float*)d_in[11];
    float* out = (float*)d_out;

    // Projections (small)
    proj_partial_kernel<<<96, 256>>>(x, Wq, Wk, Wv);
    proj_reduce_kernel<<<48, 1024>>>(bq, bk, bv);

    // Bulk cache passthrough via SM copy kernel (dominant ~2.1 GB traffic)
    copy_kernel<<<4096, 256>>>((const float4*)kvk, (const float4*)kvv,
                               (float4*)(out + OFF_K), (float4*)(out + OFF_V));
    insert_kernel<<<32, 512>>>(out, kidx);

    // Flash-decode attention on INPUT caches (row idx substituted in-kernel)
    logits_kernel<<<Bb * Hh * NCH, 256>>>(kvk, kidx);
    softmax_stats_kernel<<<Bb * Hh, 256>>>(kidx);
    av_kernel<<<Bb * Hh * NCH, 256>>>(kvv, kidx);
    av_reduce_kernel<<<16, 1024>>>();

    // Output projection + new_idx
    outproj_partial_kernel<<<32, 256>>>(Wo);
    outproj_reduce_kernel<<<16, 1024>>>(bo, kidx, out);
}

// round 3
// speedup vs baseline: 2.6270x; 1.1898x over previous
#include <cuda_runtime.h>
#include <cuda_bf16.h>
#include <math.h>

#define Bb 16
#define Ff 1024
#define Hh 16
#define Dd 64
#define Ll 8192
#define HD 1024        // H*D
#define ROWS 128       // rows per block in fused copy kernels
#define CPB (Ll / ROWS) // 64 chunks per batch

// Output layout (reference return order, flattened as float32):
//   y [B,F] | kv_key [B,L,H,D] | kv_value [B,L,H,D] | new_idx [B]
#define KV_ELEMS ((size_t)Bb * Ll * HD)
#define OFF_Y   ((size_t)0)
#define OFF_K   ((size_t)(Bb * Ff))
#define OFF_V   (OFF_K + KV_ELEMS)
#define OFF_IDX (OFF_V + KV_ELEMS)

// Scratch (device globals; 16B-aligned for float4 access)
__device__ __align__(256) float g_qkv[3 * Bb * HD];          // q,k,v after reduce
__device__ __align__(256) float g_proj_partial[3 * 8 * Bb * HD];
__device__ __align__(256) float g_logits[(size_t)Bb * Hh * Ll]; // 8 MB
__device__ float g_M[Bb * Hh];
__device__ float g_S[Bb * Hh];
__device__ __align__(256) float g_av_part[Bb * Hh * CPB * Dd];  // 4 MB
__device__ __align__(256) float g_attn[Bb * HD];
__device__ __align__(256) float g_out_partial[8 * Bb * HD];

static __device__ __forceinline__ float bf16r(float v) {
    return __bfloat162float(__float2bfloat16(v));
}

// ---------------------------------------------------------------------------
// QKV projection partials: 96 blocks = (proj 3) x (out-chunk 4) x (f-chunk 8)
// ---------------------------------------------------------------------------
__global__ void proj_partial_kernel(const float* __restrict__ x,
                                    const float* __restrict__ Wq,
                                    const float* __restrict__ Wk,
                                    const float* __restrict__ Wv) {
    int blk = blockIdx.x;
    int p  = blk >> 5;
    int oc = (blk >> 3) & 3;
    int fc = blk & 7;
    const float* W = (p == 0) ? Wq : (p == 1) ? Wk : Wv;

    __shared__ float xs[Bb][128];
    int tid = threadIdx.x;
    for (int i = tid; i < Bb * 128; i += 256) {
        int b = i >> 7, f = i & 127;
        xs[b][f] = x[b * Ff + fc * 128 + f];
    }
    __syncthreads();

    int o = oc * 256 + tid;
    float acc[Bb];
#pragma unroll
    for (int b = 0; b < Bb; b++) acc[b] = 0.0f;

    const float* Wp = W + (size_t)(fc * 128) * HD + o;
    for (int f = 0; f < 128; f++) {
        float w = Wp[(size_t)f * HD];
#pragma unroll
        for (int b = 0; b < Bb; b++) acc[b] = fmaf(xs[b][f], w, acc[b]);
    }
#pragma unroll
    for (int b = 0; b < Bb; b++)
        g_proj_partial[((size_t)(p * 8 + fc) * Bb + b) * HD + o] = acc[b];
}

__global__ void proj_reduce_kernel(const float* __restrict__ bq,
                                   const float* __restrict__ bk,
                                   const float* __restrict__ bv) {
    int i = blockIdx.x * blockDim.x + threadIdx.x;
    if (i >= 3 * Bb * HD) return;
    int p = i / (Bb * HD);
    int rem = i - p * (Bb * HD);
    int b = rem / HD, o = rem - b * HD;
    float s = ((p == 0) ? bq : (p == 1) ? bk : bv)[o];
#pragma unroll
    for (int c = 0; c < 8; c++)
        s += g_proj_partial[((size_t)(p * 8 + c) * Bb + b) * HD + o];
    g_qkv[i] = s;
}

// ---------------------------------------------------------------------------
// Kernel A: fused K copy + insert + logits.
// Block handles 128 rows of one batch. Warp w does rows w, w+8, ... (x16).
// Per float4 load, head h = 2j + lane/16, dims d = (lane%16)*4 .. +3.
// ---------------------------------------------------------------------------
__global__ __launch_bounds__(256) void copyk_logits_kernel(const float* __restrict__ kvk,
                                                           const int* __restrict__ kv_idx,
                                                           float* __restrict__ out) {
    int blk = blockIdx.x;
    int b = blk >> 6;          // CPB=64 chunks per batch
    int c = blk & 63;
    int l0 = c * ROWS;
    int kvi = kv_idx[b];
    int seq = min(kvi + 1, Ll);
    int idx = kvi % Ll;
    int tid = threadIdx.x, lane = tid & 31, warp = tid >> 5;

    __shared__ float q_s[HD];          // bf16-rounded q for this batch, 4 KB
    __shared__ float slog[Hh][ROWS];   // 8 KB
    for (int i = tid; i < HD; i += 256) q_s[i] = bf16r(g_qkv[(size_t)b * HD + i]);
    __syncthreads();

    const float4* knew4 = (const float4*)(g_qkv + (size_t)Bb * HD + (size_t)b * HD);

    for (int t = 0; t < ROWS / 8; t++) {
        int rl = warp + 8 * t;
        int l = l0 + rl;
        const float4* src = (l == idx) ? knew4
                          : (const float4*)(kvk + ((size_t)b * Ll + l) * HD);
        float4* dst = (float4*)(out + OFF_K + ((size_t)b * Ll + l) * HD);
        bool live = (l < seq);
#pragma unroll
        for (int j = 0; j < 8; j++) {
            float4 v = src[j * 32 + lane];
            dst[j * 32 + lane] = v;
            if (live) {
                int h = 2 * j + (lane >> 4);
                int d = (lane & 15) * 4;
                float p = bf16r(v.x) * q_s[h * Dd + d]
                        + bf16r(v.y) * q_s[h * Dd + d + 1]
                        + bf16r(v.z) * q_s[h * Dd + d + 2]
                        + bf16r(v.w) * q_s[h * Dd + d + 3];
                p += __shfl_down_sync(0xffffffffu, p, 8, 16);
                p += __shfl_down_sync(0xffffffffu, p, 4, 16);
                p += __shfl_down_sync(0xffffffffu, p, 2, 16);
                p += __shfl_down_sync(0xffffffffu, p, 1, 16);
                if ((lane & 15) == 0) slog[h][rl] = p * 0.125f;
            }
        }
    }
    __syncthreads();

    int lmax = min(seq - l0, ROWS);
    if (lmax > 0) {
        for (int i = tid; i < Hh * ROWS; i += 256) {
            int h = i >> 7, r = i & (ROWS - 1);
            if (r < lmax)
                g_logits[((size_t)(b * Hh + h)) * Ll + l0 + r] = slog[h][r];
        }
    }
}

// ---------------------------------------------------------------------------
// Softmax stats per (b,h): global max + sum of exp (fp32, exact ref math)
// ---------------------------------------------------------------------------
__global__ __launch_bounds__(256) void softmax_stats_kernel(const int* __restrict__ kv_idx) {
    int bh = blockIdx.x;
    int b = bh >> 4;
    int seq = min(kv_idx[b] + 1, Ll);
    const float* lg = g_logits + (size_t)bh * Ll;

    __shared__ float sred[40];
    int tid = threadIdx.x, lane = tid & 31, warp = tid >> 5;

    float m = -INFINITY;
    for (int l = tid; l < seq; l += 256) m = fmaxf(m, lg[l]);
#pragma unroll
    for (int off = 16; off > 0; off >>= 1)
        m = fmaxf(m, __shfl_down_sync(0xffffffffu, m, off));
    if (lane == 0) sred[warp] = m;
    __syncthreads();
    if (tid == 0) {
        float mm = sred[0];
#pragma unroll
        for (int w = 1; w < 8; w++) mm = fmaxf(mm, sred[w]);
        sred[32] = mm;
    }
    __syncthreads();
    m = sred[32];

    float ssum = 0.0f;
    for (int l = tid; l < seq; l += 256) ssum += expf(lg[l] - m);
#pragma unroll
    for (int off = 16; off > 0; off >>= 1)
        ssum += __shfl_down_sync(0xffffffffu, ssum, off);
    if (lane == 0) sred[warp] = ssum;
    __syncthreads();
    if (tid == 0) {
        float st = 0.0f;
#pragma unroll
        for (int w = 0; w < 8; w++) st += sred[w];
        g_M[bh] = m;
        g_S[bh] = st;
    }
}

// ---------------------------------------------------------------------------
// Kernel C: fused V copy + insert + AV partials.
// probs staged in smem per 128-row chunk; per-thread register accumulators.
// ---------------------------------------------------------------------------
__global__ __launch_bounds__(256) void copyv_av_kernel(const float* __restrict__ kvv,
                                                       const int* __restrict__ kv_idx,
                                                       float* __restrict__ out) {
    int blk = blockIdx.x;
    int b = blk >> 6;
    int c = blk & 63;
    int l0 = c * ROWS;
    int kvi = kv_idx[b];
    int seq = min(kvi + 1, Ll);
    int idx = kvi % Ll;
    int tid = threadIdx.x, lane = tid & 31, warp = tid >> 5;
    int bh0 = b * Hh;

    __shared__ float prob_s[Hh][ROWS];   // 8 KB
    __shared__ float wacc[8][HD];        // 32 KB

    // Stage bf16-rounded probs for this row chunk (0 for rows >= seq)
    for (int i = tid; i < Hh * ROWS; i += 256) {
        int h = i >> 7, r = i & (ROWS - 1);
        int l = l0 + r;
        float pb = 0.0f;
        if (l < seq) {
            float lg = g_logits[((size_t)(bh0 + h)) * Ll + l];
            float inv_s = 1.0f / g_S[bh0 + h];
            pb = bf16r(expf(lg - g_M[bh0 + h]) * inv_s);
        }
        prob_s[h][r] = pb;
    }
    __syncthreads();

    const float4* vnew4 = (const float4*)(g_qkv + (size_t)2 * Bb * HD + (size_t)b * HD);

    float acc[8][4];
#pragma unroll
    for (int j = 0; j < 8; j++)
#pragma unroll
        for (int i = 0; i < 4; i++) acc[j][i] = 0.0f;

    for (int t = 0; t < ROWS / 8; t++) {
        int rl = warp + 8 * t;
        int l = l0 + rl;
        const float4* src = (l == idx) ? vnew4
                          : (const float4*)(kvv + ((size_t)b * Ll + l) * HD);
        float4* dst = (float4*)(out + OFF_V + ((size_t)b * Ll + l) * HD);
#pragma unroll
        for (int j = 0; j < 8; j++) {
            float4 v = src[j * 32 + lane];
            dst[j * 32 + lane] = v;
            int h = 2 * j + (lane >> 4);
            float pb = prob_s[h][rl];
            acc[j][0] = fmaf(pb, bf16r(v.x), acc[j][0]);
            acc[j][1] = fmaf(pb, bf16r(v.y), acc[j][1]);
            acc[j][2] = fmaf(pb, bf16r(v.z), acc[j][2]);
            acc[j][3] = fmaf(pb, bf16r(v.w), acc[j][3]);
        }
    }

    // Dump per-warp accumulators: (h, d) slot per lane/j
#pragma unroll
    for (int j = 0; j < 8; j++) {
        int h = 2 * j + (lane >> 4);
        int d = (lane & 15) * 4;
#pragma unroll
        for (int i = 0; i < 4; i++)
            wacc[warp][h * Dd + d + i] = acc[j][i];
    }
    __syncthreads();

    // Reduce across the 8 warps -> per-chunk partial
    for (int i = tid; i < HD; i += 256) {
        float s = 0.0f;
#pragma unroll
        for (int w = 0; w < 8; w++) s += wacc[w][i];
        int h = i >> 6, d = i & 63;
        g_av_part[(((size_t)(bh0 + h)) * CPB + c) * Dd + d] = s;
    }
}

// Combine chunk partials -> attn (bf16-rounded, matches reference dtype)
__global__ void av_reduce_kernel() {
    int i = blockIdx.x * blockDim.x + threadIdx.x;   // < B*HD
    if (i >= Bb * HD) return;
    int bh = i >> 6;
    int d = i & 63;
    float t = 0.0f;
#pragma unroll
    for (int s = 0; s < CPB; s++)
        t += g_av_part[((size_t)bh * CPB + s) * Dd + d];
    g_attn[i] = bf16r(t);
}

// ---------------------------------------------------------------------------
// Output projection: y[b,f] = sum_hd attn[b,hd] * Wo[hd,f] + bo[f]
// ---------------------------------------------------------------------------
__global__ void outproj_partial_kernel(const float* __restrict__ Wo) {
    int fc = blockIdx.x >> 3;
    int hc = blockIdx.x & 7;
    __shared__ float as[Bb][128];
    int tid = threadIdx.x;
    for (int i = tid; i < Bb * 128; i += 256) {
        int b = i >> 7, j = i & 127;
        as[b][j] = g_attn[(size_t)b * HD + hc * 128 + j];
    }
    __syncthreads();

    int f = fc * 256 + tid;
    float acc[Bb];
#pragma unroll
    for (int b = 0; b < Bb; b++) acc[b] = 0.0f;
    const float* Wp = Wo + (size_t)(hc * 128) * Ff + f;
    for (int j = 0; j < 128; j++) {
        float w = Wp[(size_t)j * Ff];
#pragma unroll
        for (int b = 0; b < Bb; b++) acc[b] = fmaf(as[b][j], w, acc[b]);
    }
#pragma unroll
    for (int b = 0; b < Bb; b++)
        g_out_partial[((size_t)hc * Bb + b) * Ff + f] = acc[b];
}

__global__ void outproj_reduce_kernel(const float* __restrict__ bo,
                                      const int* __restrict__ kv_idx,
                                      float* __restrict__ out) {
    int i = blockIdx.x * blockDim.x + threadIdx.x;
    if (i < Bb * Ff) {
        int f = i & (Ff - 1);
        float s = bo[f];
#pragma unroll
        for (int c = 0; c < 8; c++)
            s += g_out_partial[(size_t)c * Bb * Ff + i];
        out[OFF_Y + i] = s;
    }
    if (blockIdx.x == 0 && threadIdx.x < Bb) {
        out[OFF_IDX + threadIdx.x] = (float)(kv_idx[threadIdx.x] + 1);
    }
}

// ---------------------------------------------------------------------------
extern "C" void kernel_launch(void* const* d_in, const int* in_sizes, int n_in,
                              void* d_out, int out_size) {
    const float* x    = (const float*)d_in[0];
    const float* kvk  = (const float*)d_in[1];
    const float* kvv  = (const float*)d_in[2];
    const int*   kidx = (const int*)  d_in[3];
    const float* Wq   = (const float*)d_in[4];
    const float* bq   = (const float*)d_in[5];
    const float* Wk   = (const float*)d_in[6];
    const float* bk   = (const float*)d_in[7];
    const float* Wv   = (const float*)d_in[8];
    const float* bv   = (const float*)d_in[9];
    const float* Wo   = (const float*)d_in[10];
    const float* bo   = (const float*)d_in[11];
    float* out = (float*)d_out;

    proj_partial_kernel<<<96, 256>>>(x, Wq, Wk, Wv);
    proj_reduce_kernel<<<48, 1024>>>(bq, bk, bv);

    copyk_logits_kernel<<<Bb * CPB, 256>>>(kvk, kidx, out);     // K copy+insert+logits
    softmax_stats_kernel<<<Bb * Hh, 256>>>(kidx);
    copyv_av_kernel<<<Bb * CPB, 256>>>(kvv, kidx, out);         // V copy+insert+AV
    av_reduce_kernel<<<16, 1024>>>();

    outproj_partial_kernel<<<32, 256>>>(Wo);
    outproj_reduce_kernel<<<16, 1024>>>(bo, kidx, out);
}

// round 5
// speedup vs baseline: 2.7192x; 1.0351x over previous
#include <cuda_runtime.h>
#include <cuda_bf16.h>
#include <math.h>

#define Bb 16
#define Ff 1024
#define Hh 16
#define Dd 64
#define Ll 8192
#define HD 1024        // H*D
#define ROWS 64        // rows per chunk in fused copy kernels
#define CPB (Ll / ROWS) // 128 chunks per batch

// Output layout: y [B,F] | kv_key [B,L,H,D] | kv_value [B,L,H,D] | new_idx [B]
#define KV_ELEMS ((size_t)Bb * Ll * HD)
#define OFF_Y   ((size_t)0)
#define OFF_K   ((size_t)(Bb * Ff))
#define OFF_V   (OFF_K + KV_ELEMS)
#define OFF_IDX (OFF_V + KV_ELEMS)

// Scratch (device globals)
__device__ __align__(256) float g_qkv[3 * Bb * HD];
__device__ __align__(256) float g_proj_partial[3 * 8 * Bb * HD];
__device__ __align__(256) float g_logits[(size_t)Bb * Hh * Ll];   // 8 MB
__device__ float g_M[Bb * Hh];
__device__ float g_S[Bb * Hh];
__device__ __align__(256) float g_av_part[(size_t)Bb * Hh * CPB * Dd]; // 8 MB
__device__ __align__(256) float g_attn[Bb * HD];
__device__ __align__(256) float g_out_partial[8 * Bb * HD];

static __device__ __forceinline__ float bf16r(float v) {
    return __bfloat162float(__float2bfloat16(v));
}

// ---------------------------------------------------------------------------
// QKV projection partials (unchanged — verified correct)
// ---------------------------------------------------------------------------
__global__ void proj_partial_kernel(const float* __restrict__ x,
                                    const float* __restrict__ Wq,
                                    const float* __restrict__ Wk,
                                    const float* __restrict__ Wv) {
    int blk = blockIdx.x;
    int p  = blk >> 5;
    int oc = (blk >> 3) & 3;
    int fc = blk & 7;
    const float* W = (p == 0) ? Wq : (p == 1) ? Wk : Wv;

    __shared__ float xs[Bb][128];
    int tid = threadIdx.x;
    for (int i = tid; i < Bb * 128; i += 256) {
        int b = i >> 7, f = i & 127;
        xs[b][f] = x[b * Ff + fc * 128 + f];
    }
    __syncthreads();

    int o = oc * 256 + tid;
    float acc[Bb];
#pragma unroll
    for (int b = 0; b < Bb; b++) acc[b] = 0.0f;

    const float* Wp = W + (size_t)(fc * 128) * HD + o;
    for (int f = 0; f < 128; f++) {
        float w = Wp[(size_t)f * HD];
#pragma unroll
        for (int b = 0; b < Bb; b++) acc[b] = fmaf(xs[b][f], w, acc[b]);
    }
#pragma unroll
    for (int b = 0; b < Bb; b++)
        g_proj_partial[((size_t)(p * 8 + fc) * Bb + b) * HD + o] = acc[b];
}

__global__ void proj_reduce_kernel(const float* __restrict__ bq,
                                   const float* __restrict__ bk,
                                   const float* __restrict__ bv) {
    int i = blockIdx.x * blockDim.x + threadIdx.x;
    if (i >= 3 * Bb * HD) return;
    int p = i / (Bb * HD);
    int rem = i - p * (Bb * HD);
    int b = rem / HD, o = rem - b * HD;
    float s = ((p == 0) ? bq : (p == 1) ? bk : bv)[o];
#pragma unroll
    for (int c = 0; c < 8; c++)
        s += g_proj_partial[((size_t)(p * 8 + c) * Bb + b) * HD + o];
    g_qkv[i] = s;
}

// ---------------------------------------------------------------------------
// Kernel A: fused K copy + insert + logits. One 64-row chunk per block.
// Batched ldcs -> stcs -> compute. float4 logits writeback.
// ---------------------------------------------------------------------------
__global__ __launch_bounds__(256) void copyk_logits_kernel(const float* __restrict__ kvk,
                                                           const int* __restrict__ kv_idx,
                                                           float* __restrict__ out) {
    int blk = blockIdx.x;               // b*CPB + c
    int b = blk >> 7;
    int c = blk & (CPB - 1);
    int l0 = c * ROWS;
    int kvi = kv_idx[b];
    int seq = min(kvi + 1, Ll);
    int idx = kvi & (Ll - 1);
    int tid = threadIdx.x, lane = tid & 31, warp = tid >> 5;
    bool chunk_live = (l0 < seq);

    __shared__ __align__(16) float q_s[HD];         // 4 KB, bf16-rounded q
    __shared__ __align__(16) float slog[Hh][ROWS];  // 4 KB

    if (chunk_live) {
        for (int i = tid; i < HD; i += 256) q_s[i] = bf16r(g_qkv[(size_t)b * HD + i]);
        __syncthreads();
    }

    const float4* knew4 = (const float4*)(g_qkv + (size_t)Bb * HD + (size_t)b * HD);

#pragma unroll
    for (int t = 0; t < ROWS / 8; t++) {
        int rl = warp + 8 * t;
        int l = l0 + rl;
        const float4* src = (l == idx) ? knew4
                          : (const float4*)(kvk + ((size_t)b * Ll + l) * HD);
        float4* dst = (float4*)(out + OFF_K + ((size_t)b * Ll + l) * HD);
        float4 v[8];
#pragma unroll
        for (int j = 0; j < 8; j++) v[j] = __ldcs(src + j * 32 + lane);
#pragma unroll
        for (int j = 0; j < 8; j++) __stcs(dst + j * 32 + lane, v[j]);
        if (l < seq) {
#pragma unroll
            for (int j = 0; j < 8; j++) {
                int h = 2 * j + (lane >> 4);
                const float* qh = q_s + h * Dd + (lane & 15) * 4;
                float p = bf16r(v[j].x) * qh[0] + bf16r(v[j].y) * qh[1]
                        + bf16r(v[j].z) * qh[2] + bf16r(v[j].w) * qh[3];
                p += __shfl_down_sync(0xffffffffu, p, 8, 16);
                p += __shfl_down_sync(0xffffffffu, p, 4, 16);
                p += __shfl_down_sync(0xffffffffu, p, 2, 16);
                p += __shfl_down_sync(0xffffffffu, p, 1, 16);
                if ((lane & 15) == 0) slog[h][rl] = p * 0.125f;
            }
        }
    }

    if (chunk_live) {
        __syncthreads();
        // 16 heads x 16 float4 = 256 float4, exactly one per thread.
        // Rows >= seq within a straddling chunk carry stale data; never read.
        int h = tid >> 4, r4 = tid & 15;
        float4 vv = ((const float4*)slog[h])[r4];
        ((float4*)(g_logits + ((size_t)(b * Hh + h)) * Ll + l0))[r4] = vv;
    }
}

// ---------------------------------------------------------------------------
// Softmax stats per (b,h): exact global max + sum of exp
// ---------------------------------------------------------------------------
__global__ __launch_bounds__(256) void softmax_stats_kernel(const int* __restrict__ kv_idx) {
    int bh = blockIdx.x;
    int b = bh >> 4;
    int seq = min(kv_idx[b] + 1, Ll);
    const float* lg = g_logits + (size_t)bh * Ll;

    __shared__ float sred[40];
    int tid = threadIdx.x, lane = tid & 31, warp = tid >> 5;

    float m = -INFINITY;
    for (int l = tid; l < seq; l += 256) m = fmaxf(m, lg[l]);
#pragma unroll
    for (int off = 16; off > 0; off >>= 1)
        m = fmaxf(m, __shfl_down_sync(0xffffffffu, m, off));
    if (lane == 0) sred[warp] = m;
    __syncthreads();
    if (tid == 0) {
        float mm = sred[0];
#pragma unroll
        for (int w = 1; w < 8; w++) mm = fmaxf(mm, sred[w]);
        sred[32] = mm;
    }
    __syncthreads();
    m = sred[32];

    float ssum = 0.0f;
    for (int l = tid; l < seq; l += 256) ssum += expf(lg[l] - m);
#pragma unroll
    for (int off = 16; off > 0; off >>= 1)
        ssum += __shfl_down_sync(0xffffffffu, ssum, off);
    if (lane == 0) sred[warp] = ssum;
    __syncthreads();
    if (tid == 0) {
        float st = 0.0f;
#pragma unroll
        for (int w = 0; w < 8; w++) st += sred[w];
        g_M[bh] = m;
        g_S[bh] = st;
    }
}

// ---------------------------------------------------------------------------
// Kernel C: fused V copy + insert + AV partials. Dead chunks: copy-only fast path.
// ---------------------------------------------------------------------------
__global__ __launch_bounds__(256) void copyv_av_kernel(const float* __restrict__ kvv,
                                                       const int* __restrict__ kv_idx,
                                                       float* __restrict__ out) {
    int blk = blockIdx.x;
    int b = blk >> 7;
    int c = blk & (CPB - 1);
    int l0 = c * ROWS;
    int kvi = kv_idx[b];
    int seq = min(kvi + 1, Ll);
    int idx = kvi & (Ll - 1);
    int tid = threadIdx.x, lane = tid & 31, warp = tid >> 5;
    int bh0 = b * Hh;

    __shared__ __align__(16) float prob_s[Hh][ROWS];  // 4 KB
    __shared__ __align__(16) float wacc[8][HD];       // 32 KB

    if (l0 >= seq) {
        // Dead chunk: pure streaming copy + zero the AV partial
#pragma unroll
        for (int t = 0; t < ROWS / 8; t++) {
            int l = l0 + warp + 8 * t;
            const float4* src = (const float4*)(kvv + ((size_t)b * Ll + l) * HD);
            float4* dst = (float4*)(out + OFF_V + ((size_t)b * Ll + l) * HD);
            float4 v[8];
#pragma unroll
            for (int j = 0; j < 8; j++) v[j] = __ldcs(src + j * 32 + lane);
#pragma unroll
            for (int j = 0; j < 8; j++) __stcs(dst + j * 32 + lane, v[j]);
        }
        for (int i = tid; i < Hh * Dd; i += 256) {
            int h = i >> 6, d = i & 63;
            g_av_part[(((size_t)(bh0 + h)) * CPB + c) * Dd + d] = 0.0f;
        }
        return;
    }

    // Stage bf16-rounded probs for this chunk: 16 heads x 16 float4, 1/thread
    {
        int h = tid >> 4, r4 = tid & 15;
        float4 lg4 = ((const float4*)(g_logits + ((size_t)(bh0 + h)) * Ll + l0))[r4];
        float m = g_M[bh0 + h];
        float inv_s = 1.0f / g_S[bh0 + h];
        int r = r4 * 4;
        float4 pv;
        pv.x = (l0 + r     < seq) ? bf16r(expf(lg4.x - m) * inv_s) : 0.0f;
        pv.y = (l0 + r + 1 < seq) ? bf16r(expf(lg4.y - m) * inv_s) : 0.0f;
        pv.z = (l0 + r + 2 < seq) ? bf16r(expf(lg4.z - m) * inv_s) : 0.0f;
        pv.w = (l0 + r + 3 < seq) ? bf16r(expf(lg4.w - m) * inv_s) : 0.0f;
        ((float4*)prob_s[h])[r4] = pv;
    }
    __syncthreads();

    const float4* vnew4 = (const float4*)(g_qkv + (size_t)2 * Bb * HD + (size_t)b * HD);

    float acc[8][4];
#pragma unroll
    for (int j = 0; j < 8; j++)
#pragma unroll
        for (int i = 0; i < 4; i++) acc[j][i] = 0.0f;

#pragma unroll
    for (int t = 0; t < ROWS / 8; t++) {
        int rl = warp + 8 * t;
        int l = l0 + rl;
        const float4* src = (l == idx) ? vnew4
                          : (const float4*)(kvv + ((size_t)b * Ll + l) * HD);
        float4* dst = (float4*)(out + OFF_V + ((size_t)b * Ll + l) * HD);
        float4 v[8];
#pragma unroll
        for (int j = 0; j < 8; j++) v[j] = __ldcs(src + j * 32 + lane);
#pragma unroll
        for (int j = 0; j < 8; j++) __stcs(dst + j * 32 + lane, v[j]);
#pragma unroll
        for (int j = 0; j < 8; j++) {
            int h = 2 * j + (lane >> 4);
            float pb = prob_s[h][rl];
            acc[j][0] = fmaf(pb, bf16r(v[j].x), acc[j][0]);
            acc[j][1] = fmaf(pb, bf16r(v[j].y), acc[j][1]);
            acc[j][2] = fmaf(pb, bf16r(v[j].z), acc[j][2]);
            acc[j][3] = fmaf(pb, bf16r(v[j].w), acc[j][3]);
        }
    }

#pragma unroll
    for (int j = 0; j < 8; j++) {
        int h = 2 * j + (lane >> 4);
        int d = (lane & 15) * 4;
#pragma unroll
        for (int i = 0; i < 4; i++)
            wacc[warp][h * Dd + d + i] = acc[j][i];
    }
    __syncthreads();

    for (int i = tid; i < HD; i += 256) {
        float s = 0.0f;
#pragma unroll
        for (int w = 0; w < 8; w++) s += wacc[w][i];
        int h = i >> 6, d = i & 63;
        g_av_part[(((size_t)(bh0 + h)) * CPB + c) * Dd + d] = s;
    }
}

// Combine chunk partials -> attn (bf16-rounded)
__global__ void av_reduce_kernel() {
    int i = blockIdx.x * blockDim.x + threadIdx.x;   // < B*HD
    if (i >= Bb * HD) return;
    int bh = i >> 6;
    int d = i & 63;
    float t = 0.0f;
#pragma unroll 8
    for (int s = 0; s < CPB; s++)
        t += g_av_part[((size_t)bh * CPB + s) * Dd + d];
    g_attn[i] = bf16r(t);
}

// ---------------------------------------------------------------------------
// Output projection
// ---------------------------------------------------------------------------
__global__ void outproj_partial_kernel(const float* __restrict__ Wo) {
    int fc = blockIdx.x >> 3;
    int hc = blockIdx.x & 7;
    __shared__ float as[Bb][128];
    int tid = threadIdx.x;
    for (int i = tid; i < Bb * 128; i += 256) {
        int b = i >> 7, j = i & 127;
        as[b][j] = g_attn[(size_t)b * HD + hc * 128 + j];
    }
    __syncthreads();

    int f = fc * 256 + tid;
    float acc[Bb];
#pragma unroll
    for (int b = 0; b < Bb; b++) acc[b] = 0.0f;
    const float* Wp = Wo + (size_t)(hc * 128) * Ff + f;
    for (int j = 0; j < 128; j++) {
        float w = Wp[(size_t)j * Ff];
#pragma unroll
        for (int b = 0; b < Bb; b++) acc[b] = fmaf(as[b][j], w, acc[b]);
    }
#pragma unroll
    for (int b = 0; b < Bb; b++)
        g_out_partial[((size_t)hc * Bb + b) * Ff + f] = acc[b];
}

__global__ void outproj_reduce_kernel(const float* __restrict__ bo,
                                      const int* __restrict__ kv_idx,
                                      float* __restrict__ out) {
    int i = blockIdx.x * blockDim.x + threadIdx.x;
    if (i < Bb * Ff) {
        int f = i & (Ff - 1);
        float s = bo[f];
#pragma unroll
        for (int c = 0; c < 8; c++)
            s += g_out_partial[(size_t)c * Bb * Ff + i];
        out[OFF_Y + i] = s;
    }
    if (blockIdx.x == 0 && threadIdx.x < Bb) {
        out[OFF_IDX + threadIdx.x] = (float)(kv_idx[threadIdx.x] + 1);
    }
}

// ---------------------------------------------------------------------------
extern "C" void kernel_launch(void* const* d_in, const int* in_sizes, int n_in,
                              void* d_out, int out_size) {
    const float* x    = (const float*)d_in[0];
    const float* kvk  = (const float*)d_in[1];
    const float* kvv  = (const float*)d_in[2];
    const int*   kidx = (const int*)  d_in[3];
    const float* Wq   = (const float*)d_in[4];
    const float* bq   = (const float*)d_in[5];
    const float* Wk   = (const float*)d_in[6];
    const float* bk   = (const float*)d_in[7];
    const float* Wv   = (const float*)d_in[8];
    const float* bv   = (const float*)d_in[9];
    const float* Wo   = (const float*)d_in[10];
    const float* bo   = (const float*)d_in[11];
    float* out = (float*)d_out;

    proj_partial_kernel<<<96, 256>>>(x, Wq, Wk, Wv);
    proj_reduce_kernel<<<48, 1024>>>(bq, bk, bv);

    copyk_logits_kernel<<<Bb * CPB, 256>>>(kvk, kidx, out);
    softmax_stats_kernel<<<Bb * Hh, 256>>>(kidx);
    copyv_av_kernel<<<Bb * CPB, 256>>>(kvv, kidx, out);
    av_reduce_kernel<<<16, 1024>>>();

    outproj_partial_kernel<<<32, 256>>>(Wo);
    outproj_reduce_kernel<<<16, 1024>>>(bo, kidx, out);
}

// round 6
// speedup vs baseline: 2.9679x; 1.0915x over previous
#include <cuda_runtime.h>
#include <cuda_bf16.h>
#include <math.h>

#define Bb 16
#define Ff 1024
#define Hh 16
#define Dd 64
#define Ll 8192
#define HD 1024        // H*D
#define ROWS 64        // rows per chunk in fused copy kernels
#define CPB (Ll / ROWS) // 128 chunks per batch
#define FCH 32         // proj f-chunks (each 32 wide)
#define OCH 32         // outproj hd-chunks (each 32 wide)

// Output layout: y [B,F] | kv_key [B,L,H,D] | kv_value [B,L,H,D] | new_idx [B]
#define KV_ELEMS ((size_t)Bb * Ll * HD)
#define OFF_Y   ((size_t)0)
#define OFF_K   ((size_t)(Bb * Ff))
#define OFF_V   (OFF_K + KV_ELEMS)
#define OFF_IDX (OFF_V + KV_ELEMS)

// Scratch (device globals)
__device__ __align__(256) float g_qkv[3 * Bb * HD];
__device__ __align__(256) float g_proj_partial[3 * FCH * Bb * HD];      // 6 MB
__device__ __align__(256) float g_logits[(size_t)Bb * Hh * Ll];         // 8 MB
__device__ float g_M[Bb * Hh];
__device__ float g_S[Bb * Hh];
__device__ __align__(256) float g_av_part[(size_t)Bb * Hh * CPB * Dd];  // 8 MB
__device__ __align__(256) float g_attn[Bb * HD];
__device__ __align__(256) float g_out_partial[OCH * Bb * Ff];           // 2 MB

static __device__ __forceinline__ float bf16r(float v) {
    return __bfloat162float(__float2bfloat16(v));
}

// ---------------------------------------------------------------------------
// QKV projection partials: grid = 3 proj x FCH f-chunks (96 blocks, 256 thr).
// Thread owns 4 contiguous outputs (float4 along HD). 32 f-iters, 16B/thr/iter.
// ---------------------------------------------------------------------------
__global__ __launch_bounds__(256) void proj_partial_kernel(const float* __restrict__ x,
                                                           const float* __restrict__ Wq,
                                                           const float* __restrict__ Wk,
                                                           const float* __restrict__ Wv) {
    int blk = blockIdx.x;
    int p  = blk / FCH;           // 0..2
    int fc = blk - p * FCH;       // 0..31
    const float* W = (p == 0) ? Wq : (p == 1) ? Wk : Wv;
    int tid = threadIdx.x;

    __shared__ float xs[Bb][Ff / FCH];   // 16 x 32
    for (int i = tid; i < Bb * 32; i += 256) {
        int b = i >> 5, f = i & 31;
        xs[b][f] = x[b * Ff + fc * 32 + f];
    }
    __syncthreads();

    float4 acc[Bb];
#pragma unroll
    for (int b = 0; b < Bb; b++) acc[b] = make_float4(0.f, 0.f, 0.f, 0.f);

    const float4* Wp = (const float4*)(W + (size_t)(fc * 32) * HD) + tid;
#pragma unroll 4
    for (int f = 0; f < 32; f++) {
        float4 w = Wp[(size_t)f * 256];
#pragma unroll
        for (int b = 0; b < Bb; b++) {
            float xv = xs[b][f];
            acc[b].x = fmaf(xv, w.x, acc[b].x);
            acc[b].y = fmaf(xv, w.y, acc[b].y);
            acc[b].z = fmaf(xv, w.z, acc[b].z);
            acc[b].w = fmaf(xv, w.w, acc[b].w);
        }
    }
#pragma unroll
    for (int b = 0; b < Bb; b++)
        ((float4*)(g_proj_partial + ((size_t)(p * FCH + fc) * Bb + b) * HD))[tid] = acc[b];
}

__global__ void proj_reduce_kernel(const float* __restrict__ bq,
                                   const float* __restrict__ bk,
                                   const float* __restrict__ bv) {
    int i = blockIdx.x * blockDim.x + threadIdx.x;   // < 3*B*HD = 49152
    if (i >= 3 * Bb * HD) return;
    int p = i / (Bb * HD);
    int rem = i - p * (Bb * HD);
    int b = rem / HD, o = rem - b * HD;
    float s = ((p == 0) ? bq : (p == 1) ? bk : bv)[o];
#pragma unroll 8
    for (int c = 0; c < FCH; c++)
        s += g_proj_partial[((size_t)(p * FCH + c) * Bb + b) * HD + o];
    g_qkv[i] = s;
}

// ---------------------------------------------------------------------------
// Kernel A: fused K copy + insert + logits (unchanged from R5 — proven)
// ---------------------------------------------------------------------------
__global__ __launch_bounds__(256) void copyk_logits_kernel(const float* __restrict__ kvk,
                                                           const int* __restrict__ kv_idx,
                                                           float* __restrict__ out) {
    int blk = blockIdx.x;
    int b = blk >> 7;
    int c = blk & (CPB - 1);
    int l0 = c * ROWS;
    int kvi = kv_idx[b];
    int seq = min(kvi + 1, Ll);
    int idx = kvi & (Ll - 1);
    int tid = threadIdx.x, lane = tid & 31, warp = tid >> 5;
    bool chunk_live = (l0 < seq);

    __shared__ __align__(16) float q_s[HD];
    __shared__ __align__(16) float slog[Hh][ROWS];

    if (chunk_live) {
        for (int i = tid; i < HD; i += 256) q_s[i] = bf16r(g_qkv[(size_t)b * HD + i]);
        __syncthreads();
    }

    const float4* knew4 = (const float4*)(g_qkv + (size_t)Bb * HD + (size_t)b * HD);

#pragma unroll
    for (int t = 0; t < ROWS / 8; t++) {
        int rl = warp + 8 * t;
        int l = l0 + rl;
        const float4* src = (l == idx) ? knew4
                          : (const float4*)(kvk + ((size_t)b * Ll + l) * HD);
        float4* dst = (float4*)(out + OFF_K + ((size_t)b * Ll + l) * HD);
        float4 v[8];
#pragma unroll
        for (int j = 0; j < 8; j++) v[j] = __ldcs(src + j * 32 + lane);
#pragma unroll
        for (int j = 0; j < 8; j++) __stcs(dst + j * 32 + lane, v[j]);
        if (l < seq) {
#pragma unroll
            for (int j = 0; j < 8; j++) {
                int h = 2 * j + (lane >> 4);
                const float* qh = q_s + h * Dd + (lane & 15) * 4;
                float p = bf16r(v[j].x) * qh[0] + bf16r(v[j].y) * qh[1]
                        + bf16r(v[j].z) * qh[2] + bf16r(v[j].w) * qh[3];
                p += __shfl_down_sync(0xffffffffu, p, 8, 16);
                p += __shfl_down_sync(0xffffffffu, p, 4, 16);
                p += __shfl_down_sync(0xffffffffu, p, 2, 16);
                p += __shfl_down_sync(0xffffffffu, p, 1, 16);
                if ((lane & 15) == 0) slog[h][rl] = p * 0.125f;
            }
        }
    }

    if (chunk_live) {
        __syncthreads();
        int h = tid >> 4, r4 = tid & 15;
        float4 vv = ((const float4*)slog[h])[r4];
        ((float4*)(g_logits + ((size_t)(b * Hh + h)) * Ll + l0))[r4] = vv;
    }
}

// ---------------------------------------------------------------------------
// Softmax stats per (b,h): exact global max + sum of exp
// ---------------------------------------------------------------------------
__global__ __launch_bounds__(256) void softmax_stats_kernel(const int* __restrict__ kv_idx) {
    int bh = blockIdx.x;
    int b = bh >> 4;
    int seq = min(kv_idx[b] + 1, Ll);
    const float* lg = g_logits + (size_t)bh * Ll;

    __shared__ float sred[40];
    int tid = threadIdx.x, lane = tid & 31, warp = tid >> 5;

    float m = -INFINITY;
    for (int l = tid; l < seq; l += 256) m = fmaxf(m, lg[l]);
#pragma unroll
    for (int off = 16; off > 0; off >>= 1)
        m = fmaxf(m, __shfl_down_sync(0xffffffffu, m, off));
    if (lane == 0) sred[warp] = m;
    __syncthreads();
    if (tid == 0) {
        float mm = sred[0];
#pragma unroll
        for (int w = 1; w < 8; w++) mm = fmaxf(mm, sred[w]);
        sred[32] = mm;
    }
    __syncthreads();
    m = sred[32];

    float ssum = 0.0f;
    for (int l = tid; l < seq; l += 256) ssum += expf(lg[l] - m);
#pragma unroll
    for (int off = 16; off > 0; off >>= 1)
        ssum += __shfl_down_sync(0xffffffffu, ssum, off);
    if (lane == 0) sred[warp] = ssum;
    __syncthreads();
    if (tid == 0) {
        float st = 0.0f;
#pragma unroll
        for (int w = 0; w < 8; w++) st += sred[w];
        g_M[bh] = m;
        g_S[bh] = st;
    }
}

// ---------------------------------------------------------------------------
// Kernel C: fused V copy + insert + AV partials. Dead chunks: copy only
// (no zero partial stores — av_reduce skips dead chunks).
// ---------------------------------------------------------------------------
__global__ __launch_bounds__(256) void copyv_av_kernel(const float* __restrict__ kvv,
                                                       const int* __restrict__ kv_idx,
                                                       float* __restrict__ out) {
    int blk = blockIdx.x;
    int b = blk >> 7;
    int c = blk & (CPB - 1);
    int l0 = c * ROWS;
    int kvi = kv_idx[b];
    int seq = min(kvi + 1, Ll);
    int idx = kvi & (Ll - 1);
    int tid = threadIdx.x, lane = tid & 31, warp = tid >> 5;
    int bh0 = b * Hh;

    __shared__ __align__(16) float prob_s[Hh][ROWS];
    __shared__ __align__(16) float wacc[8][HD];

    if (l0 >= seq) {
        // Dead chunk: pure streaming copy
#pragma unroll
        for (int t = 0; t < ROWS / 8; t++) {
            int l = l0 + warp + 8 * t;
            const float4* src = (const float4*)(kvv + ((size_t)b * Ll + l) * HD);
            float4* dst = (float4*)(out + OFF_V + ((size_t)b * Ll + l) * HD);
            float4 v[8];
#pragma unroll
            for (int j = 0; j < 8; j++) v[j] = __ldcs(src + j * 32 + lane);
#pragma unroll
            for (int j = 0; j < 8; j++) __stcs(dst + j * 32 + lane, v[j]);
        }
        return;
    }

    // Stage bf16-rounded probs (0 for rows >= seq)
    {
        int h = tid >> 4, r4 = tid & 15;
        float4 lg4 = ((const float4*)(g_logits + ((size_t)(bh0 + h)) * Ll + l0))[r4];
        float m = g_M[bh0 + h];
        float inv_s = 1.0f / g_S[bh0 + h];
        int r = r4 * 4;
        float4 pv;
        pv.x = (l0 + r     < seq) ? bf16r(expf(lg4.x - m) * inv_s) : 0.0f;
        pv.y = (l0 + r + 1 < seq) ? bf16r(expf(lg4.y - m) * inv_s) : 0.0f;
        pv.z = (l0 + r + 2 < seq) ? bf16r(expf(lg4.z - m) * inv_s) : 0.0f;
        pv.w = (l0 + r + 3 < seq) ? bf16r(expf(lg4.w - m) * inv_s) : 0.0f;
        ((float4*)prob_s[h])[r4] = pv;
    }
    __syncthreads();

    const float4* vnew4 = (const float4*)(g_qkv + (size_t)2 * Bb * HD + (size_t)b * HD);

    float acc[8][4];
#pragma unroll
    for (int j = 0; j < 8; j++)
#pragma unroll
        for (int i = 0; i < 4; i++) acc[j][i] = 0.0f;

#pragma unroll
    for (int t = 0; t < ROWS / 8; t++) {
        int rl = warp + 8 * t;
        int l = l0 + rl;
        const float4* src = (l == idx) ? vnew4
                          : (const float4*)(kvv + ((size_t)b * Ll + l) * HD);
        float4* dst = (float4*)(out + OFF_V + ((size_t)b * Ll + l) * HD);
        float4 v[8];
#pragma unroll
        for (int j = 0; j < 8; j++) v[j] = __ldcs(src + j * 32 + lane);
#pragma unroll
        for (int j = 0; j < 8; j++) __stcs(dst + j * 32 + lane, v[j]);
#pragma unroll
        for (int j = 0; j < 8; j++) {
            int h = 2 * j + (lane >> 4);
            float pb = prob_s[h][rl];
            acc[j][0] = fmaf(pb, bf16r(v[j].x), acc[j][0]);
            acc[j][1] = fmaf(pb, bf16r(v[j].y), acc[j][1]);
            acc[j][2] = fmaf(pb, bf16r(v[j].z), acc[j][2]);
            acc[j][3] = fmaf(pb, bf16r(v[j].w), acc[j][3]);
        }
    }

#pragma unroll
    for (int j = 0; j < 8; j++) {
        int h = 2 * j + (lane >> 4);
        int d = (lane & 15) * 4;
#pragma unroll
        for (int i = 0; i < 4; i++)
            wacc[warp][h * Dd + d + i] = acc[j][i];
    }
    __syncthreads();

    for (int i = tid; i < HD; i += 256) {
        float s = 0.0f;
#pragma unroll
        for (int w = 0; w < 8; w++) s += wacc[w][i];
        int h = i >> 6, d = i & 63;
        g_av_part[(((size_t)(bh0 + h)) * CPB + c) * Dd + d] = s;
    }
}

// Combine live chunk partials -> attn (bf16-rounded). 128 blocks x 128 thr.
__global__ __launch_bounds__(128) void av_reduce_kernel(const int* __restrict__ kv_idx) {
    int i = blockIdx.x * 128 + threadIdx.x;   // < B*HD = 16384
    int bh = i >> 6;
    int d = i & 63;
    int b = bh >> 4;
    int seq = min(kv_idx[b] + 1, Ll);
    int smax = (seq + ROWS - 1) / ROWS;       // live chunks only
    const float* src = g_av_part + (size_t)bh * CPB * Dd + d;
    float t = 0.0f;
#pragma unroll 4
    for (int s = 0; s < smax; s++)
        t += src[(size_t)s * Dd];
    g_attn[i] = bf16r(t);
}

// ---------------------------------------------------------------------------
// Output projection: grid = OCH hd-chunks (32 blocks, 256 thr), float4 along F
// ---------------------------------------------------------------------------
__global__ __launch_bounds__(256) void outproj_partial_kernel(const float* __restrict__ Wo) {
    int hc = blockIdx.x;         // 0..31, chunk of 32 hd
    int tid = threadIdx.x;

    __shared__ float as[Bb][HD / OCH];   // 16 x 32
    for (int i = tid; i < Bb * 32; i += 256) {
        int b = i >> 5, j = i & 31;
        as[b][j] = g_attn[(size_t)b * HD + hc * 32 + j];
    }
    __syncthreads();

    float4 acc[Bb];
#pragma unroll
    for (int b = 0; b < Bb; b++) acc[b] = make_float4(0.f, 0.f, 0.f, 0.f);

    const float4* Wp = (const float4*)(Wo + (size_t)(hc * 32) * Ff) + tid;
#pragma unroll 4
    for (int j = 0; j < 32; j++) {
        float4 w = Wp[(size_t)j * 256];
#pragma unroll
        for (int b = 0; b < Bb; b++) {
            float av = as[b][j];
            acc[b].x = fmaf(av, w.x, acc[b].x);
            acc[b].y = fmaf(av, w.y, acc[b].y);
            acc[b].z = fmaf(av, w.z, acc[b].z);
            acc[b].w = fmaf(av, w.w, acc[b].w);
        }
    }
#pragma unroll
    for (int b = 0; b < Bb; b++)
        ((float4*)(g_out_partial + ((size_t)hc * Bb + b) * Ff))[tid] = acc[b];
}

__global__ void outproj_reduce_kernel(const float* __restrict__ bo,
                                      const int* __restrict__ kv_idx,
                                      float* __restrict__ out) {
    int i = blockIdx.x * blockDim.x + threadIdx.x;   // < B*F = 16384
    if (i < Bb * Ff) {
        int f = i & (Ff - 1);
        float s = bo[f];
#pragma unroll 8
        for (int c = 0; c < OCH; c++)
            s += g_out_partial[(size_t)c * Bb * Ff + i];
        out[OFF_Y + i] = s;
    }
    if (blockIdx.x == 0 && threadIdx.x < Bb) {
        out[OFF_IDX + threadIdx.x] = (float)(kv_idx[threadIdx.x] + 1);
    }
}

// ---------------------------------------------------------------------------
extern "C" void kernel_launch(void* const* d_in, const int* in_sizes, int n_in,
                              void* d_out, int out_size) {
    const float* x    = (const float*)d_in[0];
    const float* kvk  = (const float*)d_in[1];
    const float* kvv  = (const float*)d_in[2];
    const int*   kidx = (const int*)  d_in[3];
    const float* Wq   = (const float*)d_in[4];
    const float* bq   = (const float*)d_in[5];
    const float* Wk   = (const float*)d_in[6];
    const float* bk   = (const float*)d_in[7];
    const float* Wv   = (const float*)d_in[8];
    const float* bv   = (const float*)d_in[9];
    const float* Wo   = (const float*)d_in[10];
    const float* bo   = (const float*)d_in[11];
    float* out = (float*)d_out;

    proj_partial_kernel<<<3 * FCH, 256>>>(x, Wq, Wk, Wv);
    proj_reduce_kernel<<<48, 1024>>>(bq, bk, bv);

    copyk_logits_kernel<<<Bb * CPB, 256>>>(kvk, kidx, out);
    softmax_stats_kernel<<<Bb * Hh, 256>>>(kidx);
    copyv_av_kernel<<<Bb * CPB, 256>>>(kvv, kidx, out);
    av_reduce_kernel<<<Bb * HD / 128, 128>>>(kidx);

    outproj_partial_kernel<<<OCH, 256>>>(Wo);
    outproj_reduce_kernel<<<16, 1024>>>(bo, kidx, out);
}

// round 7
// speedup vs baseline: 2.9682x; 1.0001x over previous
#include <cuda_runtime.h>
#include <cuda_bf16.h>
#include <math.h>

#define Bb 16
#define Ff 1024
#define Hh 16
#define Dd 64
#define Ll 8192
#define HD 1024        // H*D
#define ROWS 64        // rows per chunk in fused copy kernels
#define CPB (Ll / ROWS) // 128 chunks per batch
#define FCH 32         // proj f-chunks (each 32 wide)
#define OCH 32         // outproj hd-chunks (each 32 wide)

// Output layout: y [B,F] | kv_key [B,L,H,D] | kv_value [B,L,H,D] | new_idx [B]
#define KV_ELEMS ((size_t)Bb * Ll * HD)
#define OFF_Y   ((size_t)0)
#define OFF_K   ((size_t)(Bb * Ff))
#define OFF_V   (OFF_K + KV_ELEMS)
#define OFF_IDX (OFF_V + KV_ELEMS)

// Scratch (device globals)
__device__ __align__(256) float g_qkv[3 * Bb * HD];
__device__ __align__(256) float g_proj_partial[3 * FCH * Bb * HD];
__device__ __align__(256) float g_logits[(size_t)Bb * Hh * Ll];         // 8 MB
__device__ float g_M[Bb * Hh];
__device__ float g_S[Bb * Hh];
__device__ __align__(256) float g_av_part[(size_t)Bb * Hh * CPB * Dd];  // 8 MB
__device__ __align__(256) float g_attn[Bb * HD];
__device__ __align__(256) float g_out_partial[OCH * Bb * Ff];

static __device__ __forceinline__ float bf16r(float v) {
    return __bfloat162float(__float2bfloat16(v));
}

// Packed bf16 round of two floats; expansion back to f32 is the exact
// bf16->f32 conversion (bit shift). 3 instr per pair vs 4 scalar.
static __device__ __forceinline__ void bf16r2(float a, float b, float& ra, float& rb) {
    __nv_bfloat162 t = __floats2bfloat162_rn(a, b);   // .x=a(lo16), .y=b(hi16)
    unsigned u = *reinterpret_cast<unsigned*>(&t);
    ra = __uint_as_float(u << 16);
    rb = __uint_as_float(u & 0xffff0000u);
}

// ---------------------------------------------------------------------------
// QKV projection partials (unchanged from R6)
// ---------------------------------------------------------------------------
__global__ __launch_bounds__(256) void proj_partial_kernel(const float* __restrict__ x,
                                                           const float* __restrict__ Wq,
                                                           const float* __restrict__ Wk,
                                                           const float* __restrict__ Wv) {
    int blk = blockIdx.x;
    int p  = blk / FCH;
    int fc = blk - p * FCH;
    const float* W = (p == 0) ? Wq : (p == 1) ? Wk : Wv;
    int tid = threadIdx.x;

    __shared__ float xs[Bb][Ff / FCH];
    for (int i = tid; i < Bb * 32; i += 256) {
        int b = i >> 5, f = i & 31;
        xs[b][f] = x[b * Ff + fc * 32 + f];
    }
    __syncthreads();

    float4 acc[Bb];
#pragma unroll
    for (int b = 0; b < Bb; b++) acc[b] = make_float4(0.f, 0.f, 0.f, 0.f);

    const float4* Wp = (const float4*)(W + (size_t)(fc * 32) * HD) + tid;
#pragma unroll 4
    for (int f = 0; f < 32; f++) {
        float4 w = Wp[(size_t)f * 256];
#pragma unroll
        for (int b = 0; b < Bb; b++) {
            float xv = xs[b][f];
            acc[b].x = fmaf(xv, w.x, acc[b].x);
            acc[b].y = fmaf(xv, w.y, acc[b].y);
            acc[b].z = fmaf(xv, w.z, acc[b].z);
            acc[b].w = fmaf(xv, w.w, acc[b].w);
        }
    }
#pragma unroll
    for (int b = 0; b < Bb; b++)
        ((float4*)(g_proj_partial + ((size_t)(p * FCH + fc) * Bb + b) * HD))[tid] = acc[b];
}

__global__ void proj_reduce_kernel(const float* __restrict__ bq,
                                   const float* __restrict__ bk,
                                   const float* __restrict__ bv) {
    int i = blockIdx.x * blockDim.x + threadIdx.x;
    if (i >= 3 * Bb * HD) return;
    int p = i / (Bb * HD);
    int rem = i - p * (Bb * HD);
    int b = rem / HD, o = rem - b * HD;
    float s = ((p == 0) ? bq : (p == 1) ? bk : bv)[o];
#pragma unroll 8
    for (int c = 0; c < FCH; c++)
        s += g_proj_partial[((size_t)(p * FCH + c) * Bb + b) * HD + o];
    g_qkv[i] = s;
}

// Tiny prep kernel: writes new_idx. ALSO serves as launch-order shim so that
// copyk_logits is the 4th kernel launch (the one ncu profiles).
__global__ void prep_kernel(const int* __restrict__ kv_idx, float* __restrict__ out) {
    if (threadIdx.x < Bb)
        out[OFF_IDX + threadIdx.x] = (float)(kv_idx[threadIdx.x] + 1);
}

// ---------------------------------------------------------------------------
// Kernel A: fused K copy + insert + logits.
// Butterfly multi-reduce: all 8 per-lane dot partials reduced through one
// 4-stage XOR cascade (same pairwise summation tree as shfl_down 8/4/2/1,
// so numerics are bit-identical to previous rounds).
// After the cascade, lane (within its 16-lane half) holds the full sum for
// head h = 2*((lane>>1)&7) + (lane>>4); lanes with (lane&1)==0 store.
// ---------------------------------------------------------------------------
__global__ __launch_bounds__(256) void copyk_logits_kernel(const float* __restrict__ kvk,
                                                           const int* __restrict__ kv_idx,
                                                           float* __restrict__ out) {
    int blk = blockIdx.x;
    int b = blk >> 7;
    int c = blk & (CPB - 1);
    int l0 = c * ROWS;
    int kvi = kv_idx[b];
    int seq = min(kvi + 1, Ll);
    int idx = kvi & (Ll - 1);
    int tid = threadIdx.x, lane = tid & 31, warp = tid >> 5;
    bool chunk_live = (l0 < seq);

    __shared__ __align__(16) float q_s[HD];
    __shared__ __align__(16) float slog[Hh][ROWS];

    if (chunk_live) {
        for (int i = tid; i < HD; i += 256) q_s[i] = bf16r(g_qkv[(size_t)b * HD + i]);
        __syncthreads();
    }

    const float4* knew4 = (const float4*)(g_qkv + (size_t)Bb * HD + (size_t)b * HD);

    bool s3 = (lane & 8) != 0;
    bool s2 = (lane & 4) != 0;
    bool s1 = (lane & 2) != 0;
    int h_out = 2 * ((lane >> 1) & 7) + (lane >> 4);

#pragma unroll
    for (int t = 0; t < ROWS / 8; t++) {
        int rl = warp + 8 * t;
        int l = l0 + rl;
        const float4* src = (l == idx) ? knew4
                          : (const float4*)(kvk + ((size_t)b * Ll + l) * HD);
        float4* dst = (float4*)(out + OFF_K + ((size_t)b * Ll + l) * HD);
        float4 v[8];
#pragma unroll
        for (int j = 0; j < 8; j++) v[j] = __ldcs(src + j * 32 + lane);
#pragma unroll
        for (int j = 0; j < 8; j++) __stcs(dst + j * 32 + lane, v[j]);
        if (l < seq) {
            float p[8];
#pragma unroll
            for (int j = 0; j < 8; j++) {
                int h = 2 * j + (lane >> 4);
                const float* qh = q_s + h * Dd + (lane & 15) * 4;
                float r0, r1, r2, r3;
                bf16r2(v[j].x, v[j].y, r0, r1);
                bf16r2(v[j].z, v[j].w, r2, r3);
                p[j] = r0 * qh[0] + r1 * qh[1] + r2 * qh[2] + r3 * qh[3];
            }
            // Stage A: reduce over lane bit 3; j2 -> lane bit 3
            float a0[4];
#pragma unroll
            for (int m = 0; m < 4; m++) {
                float send = s3 ? p[m] : p[m + 4];
                float r = __shfl_xor_sync(0xffffffffu, send, 8, 16);
                float keep = s3 ? p[m + 4] : p[m];
                a0[m] = keep + r;
            }
            // Stage B: bit 2; j1 -> lane bit 2
            float b0[2];
#pragma unroll
            for (int m = 0; m < 2; m++) {
                float send = s2 ? a0[m] : a0[m + 2];
                float r = __shfl_xor_sync(0xffffffffu, send, 4, 16);
                float keep = s2 ? a0[m + 2] : a0[m];
                b0[m] = keep + r;
            }
            // Stage C: bit 1; j0 -> lane bit 1
            {
                float send = s1 ? b0[0] : b0[1];
                float r = __shfl_xor_sync(0xffffffffu, send, 2, 16);
                float keep = s1 ? b0[1] : b0[0];
                b0[0] = keep + r;
            }
            // Stage D: bit 0 (plain pair reduce)
            b0[0] += __shfl_xor_sync(0xffffffffu, b0[0], 1, 16);
            if ((lane & 1) == 0) slog[h_out][rl] = b0[0] * 0.125f;
        }
    }

    if (chunk_live) {
        __syncthreads();
        int h = tid >> 4, r4 = tid & 15;
        float4 vv = ((const float4*)slog[h])[r4];
        ((float4*)(g_logits + ((size_t)(b * Hh + h)) * Ll + l0))[r4] = vv;
    }
}

// ---------------------------------------------------------------------------
// Softmax stats per (b,h): exact global max + sum of exp
// ---------------------------------------------------------------------------
__global__ __launch_bounds__(256) void softmax_stats_kernel(const int* __restrict__ kv_idx) {
    int bh = blockIdx.x;
    int b = bh >> 4;
    int seq = min(kv_idx[b] + 1, Ll);
    const float* lg = g_logits + (size_t)bh * Ll;

    __shared__ float sred[40];
    int tid = threadIdx.x, lane = tid & 31, warp = tid >> 5;

    float m = -INFINITY;
    for (int l = tid; l < seq; l += 256) m = fmaxf(m, lg[l]);
#pragma unroll
    for (int off = 16; off > 0; off >>= 1)
        m = fmaxf(m, __shfl_down_sync(0xffffffffu, m, off));
    if (lane == 0) sred[warp] = m;
    __syncthreads();
    if (tid == 0) {
        float mm = sred[0];
#pragma unroll
        for (int w = 1; w < 8; w++) mm = fmaxf(mm, sred[w]);
        sred[32] = mm;
    }
    __syncthreads();
    m = sred[32];

    float ssum = 0.0f;
    for (int l = tid; l < seq; l += 256) ssum += expf(lg[l] - m);
#pragma unroll
    for (int off = 16; off > 0; off >>= 1)
        ssum += __shfl_down_sync(0xffffffffu, ssum, off);
    if (lane == 0) sred[warp] = ssum;
    __syncthreads();
    if (tid == 0) {
        float st = 0.0f;
#pragma unroll
        for (int w = 0; w < 8; w++) st += sred[w];
        g_M[bh] = m;
        g_S[bh] = st;
    }
}

// ---------------------------------------------------------------------------
// Kernel C: fused V copy + insert + AV partials (packed bf16 converts)
// ---------------------------------------------------------------------------
__global__ __launch_bounds__(256) void copyv_av_kernel(const float* __restrict__ kvv,
                                                       const int* __restrict__ kv_idx,
                                                       float* __restrict__ out) {
    int blk = blockIdx.x;
    int b = blk >> 7;
    int c = blk & (CPB - 1);
    int l0 = c * ROWS;
    int kvi = kv_idx[b];
    int seq = min(kvi + 1, Ll);
    int idx = kvi & (Ll - 1);
    int tid = threadIdx.x, lane = tid & 31, warp = tid >> 5;
    int bh0 = b * Hh;

    __shared__ __align__(16) float prob_s[Hh][ROWS];
    __shared__ __align__(16) float wacc[8][HD];

    if (l0 >= seq) {
#pragma unroll
        for (int t = 0; t < ROWS / 8; t++) {
            int l = l0 + warp + 8 * t;
            const float4* src = (const float4*)(kvv + ((size_t)b * Ll + l) * HD);
            float4* dst = (float4*)(out + OFF_V + ((size_t)b * Ll + l) * HD);
            float4 v[8];
#pragma unroll
            for (int j = 0; j < 8; j++) v[j] = __ldcs(src + j * 32 + lane);
#pragma unroll
            for (int j = 0; j < 8; j++) __stcs(dst + j * 32 + lane, v[j]);
        }
        return;
    }

    {
        int h = tid >> 4, r4 = tid & 15;
        float4 lg4 = ((const float4*)(g_logits + ((size_t)(bh0 + h)) * Ll + l0))[r4];
        float m = g_M[bh0 + h];
        float inv_s = 1.0f / g_S[bh0 + h];
        int r = r4 * 4;
        float4 pv;
        pv.x = (l0 + r     < seq) ? bf16r(expf(lg4.x - m) * inv_s) : 0.0f;
        pv.y = (l0 + r + 1 < seq) ? bf16r(expf(lg4.y - m) * inv_s) : 0.0f;
        pv.z = (l0 + r + 2 < seq) ? bf16r(expf(lg4.z - m) * inv_s) : 0.0f;
        pv.w = (l0 + r + 3 < seq) ? bf16r(expf(lg4.w - m) * inv_s) : 0.0f;
        ((float4*)prob_s[h])[r4] = pv;
    }
    __syncthreads();

    const float4* vnew4 = (const float4*)(g_qkv + (size_t)2 * Bb * HD + (size_t)b * HD);

    float acc[8][4];
#pragma unroll
    for (int j = 0; j < 8; j++)
#pragma unroll
        for (int i = 0; i < 4; i++) acc[j][i] = 0.0f;

#pragma unroll
    for (int t = 0; t < ROWS / 8; t++) {
        int rl = warp + 8 * t;
        int l = l0 + rl;
        const float4* src = (l == idx) ? vnew4
                          : (const float4*)(kvv + ((size_t)b * Ll + l) * HD);
        float4* dst = (float4*)(out + OFF_V + ((size_t)b * Ll + l) * HD);
        float4 v[8];
#pragma unroll
        for (int j = 0; j < 8; j++) v[j] = __ldcs(src + j * 32 + lane);
#pragma unroll
        for (int j = 0; j < 8; j++) __stcs(dst + j * 32 + lane, v[j]);
#pragma unroll
        for (int j = 0; j < 8; j++) {
            int h = 2 * j + (lane >> 4);
            float pb = prob_s[h][rl];
            float r0, r1, r2, r3;
            bf16r2(v[j].x, v[j].y, r0, r1);
            bf16r2(v[j].z, v[j].w, r2, r3);
            acc[j][0] = fmaf(pb, r0, acc[j][0]);
            acc[j][1] = fmaf(pb, r1, acc[j][1]);
            acc[j][2] = fmaf(pb, r2, acc[j][2]);
            acc[j][3] = fmaf(pb, r3, acc[j][3]);
        }
    }

#pragma unroll
    for (int j = 0; j < 8; j++) {
        int h = 2 * j + (lane >> 4);
        int d = (lane & 15) * 4;
#pragma unroll
        for (int i = 0; i < 4; i++)
            wacc[warp][h * Dd + d + i] = acc[j][i];
    }
    __syncthreads();

    for (int i = tid; i < HD; i += 256) {
        float s = 0.0f;
#pragma unroll
        for (int w = 0; w < 8; w++) s += wacc[w][i];
        int h = i >> 6, d = i & 63;
        g_av_part[(((size_t)(bh0 + h)) * CPB + c) * Dd + d] = s;
    }
}

// Combine live chunk partials -> attn (bf16-rounded)
__global__ __launch_bounds__(128) void av_reduce_kernel(const int* __restrict__ kv_idx) {
    int i = blockIdx.x * 128 + threadIdx.x;
    int bh = i >> 6;
    int d = i & 63;
    int b = bh >> 4;
    int seq = min(kv_idx[b] + 1, Ll);
    int smax = (seq + ROWS - 1) / ROWS;
    const float* src = g_av_part + (size_t)bh * CPB * Dd + d;
    float t = 0.0f;
#pragma unroll 4
    for (int s = 0; s < smax; s++)
        t += src[(size_t)s * Dd];
    g_attn[i] = bf16r(t);
}

// ---------------------------------------------------------------------------
// Output projection (unchanged from R6)
// ---------------------------------------------------------------------------
__global__ __launch_bounds__(256) void outproj_partial_kernel(const float* __restrict__ Wo) {
    int hc = blockIdx.x;
    int tid = threadIdx.x;

    __shared__ float as[Bb][HD / OCH];
    for (int i = tid; i < Bb * 32; i += 256) {
        int b = i >> 5, j = i & 31;
        as[b][j] = g_attn[(size_t)b * HD + hc * 32 + j];
    }
    __syncthreads();

    float4 acc[Bb];
#pragma unroll
    for (int b = 0; b < Bb; b++) acc[b] = make_float4(0.f, 0.f, 0.f, 0.f);

    const float4* Wp = (const float4*)(Wo + (size_t)(hc * 32) * Ff) + tid;
#pragma unroll 4
    for (int j = 0; j < 32; j++) {
        float4 w = Wp[(size_t)j * 256];
#pragma unroll
        for (int b = 0; b < Bb; b++) {
            float av = as[b][j];
            acc[b].x = fmaf(av, w.x, acc[b].x);
            acc[b].y = fmaf(av, w.y, acc[b].y);
            acc[b].z = fmaf(av, w.z, acc[b].z);
            acc[b].w = fmaf(av, w.w, acc[b].w);
        }
    }
#pragma unroll
    for (int b = 0; b < Bb; b++)
        ((float4*)(g_out_partial + ((size_t)hc * Bb + b) * Ff))[tid] = acc[b];
}

__global__ void outproj_reduce_kernel(const float* __restrict__ bo,
                                      float* __restrict__ out) {
    int i = blockIdx.x * blockDim.x + threadIdx.x;
    if (i < Bb * Ff) {
        int f = i & (Ff - 1);
        float s = bo[f];
#pragma unroll 8
        for (int c = 0; c < OCH; c++)
            s += g_out_partial[(size_t)c * Bb * Ff + i];
        out[OFF_Y + i] = s;
    }
}

// ---------------------------------------------------------------------------
extern "C" void kernel_launch(void* const* d_in, const int* in_sizes, int n_in,
                              void* d_out, int out_size) {
    const float* x    = (const float*)d_in[0];
    const float* kvk  = (const float*)d_in[1];
    const float* kvv  = (const float*)d_in[2];
    const int*   kidx = (const int*)  d_in[3];
    const float* Wq   = (const float*)d_in[4];
    const float* bq   = (const float*)d_in[5];
    const float* Wk   = (const float*)d_in[6];
    const float* bk   = (const float*)d_in[7];
    const float* Wv   = (const float*)d_in[8];
    const float* bv   = (const float*)d_in[9];
    const float* Wo   = (const float*)d_in[10];
    const float* bo   = (const float*)d_in[11];
    float* out = (float*)d_out;

    proj_partial_kernel<<<3 * FCH, 256>>>(x, Wq, Wk, Wv);     // 1
    proj_reduce_kernel<<<48, 1024>>>(bq, bk, bv);             // 2
    prep_kernel<<<1, 32>>>(kidx, out);                        // 3 (shim: makes copyk the profiled #4)
    copyk_logits_kernel<<<Bb * CPB, 256>>>(kvk, kidx, out);   // 4 <- ncu target
    softmax_stats_kernel<<<Bb * Hh, 256>>>(kidx);             // 5
    copyv_av_kernel<<<Bb * CPB, 256>>>(kvv, kidx, out);       // 6
    av_reduce_kernel<<<Bb * HD / 128, 128>>>(kidx);           // 7
    outproj_partial_kernel<<<OCH, 256>>>(Wo);                 // 8
    outproj_reduce_kernel<<<16, 1024>>>(bo, out);             // 9
}

// round 8
// speedup vs baseline: 2.9966x; 1.0096x over previous
#include <cuda_runtime.h>
#include <cuda_bf16.h>
#include <math.h>

#define Bb 16
#define Ff 1024
#define Hh 16
#define Dd 64
#define Ll 8192
#define HD 1024        // H*D
#define ROWS 64        // rows per chunk in fused copy kernels
#define CPB (Ll / ROWS) // 128 chunks per batch
#define FCH 32         // proj f-chunks (each 32 wide)
#define OCH 32         // outproj hd-chunks (each 32 wide)

// Output layout: y [B,F] | kv_key [B,L,H,D] | kv_value [B,L,H,D] | new_idx [B]
#define KV_ELEMS ((size_t)Bb * Ll * HD)
#define OFF_Y   ((size_t)0)
#define OFF_K   ((size_t)(Bb * Ff))
#define OFF_V   (OFF_K + KV_ELEMS)
#define OFF_IDX (OFF_V + KV_ELEMS)

// Scratch (device globals)
__device__ __align__(256) float g_qkv[3 * Bb * HD];
__device__ __align__(256) float g_proj_partial[3 * FCH * Bb * HD];
__device__ __align__(256) float g_logits[(size_t)Bb * Hh * Ll];         // 8 MB
__device__ __align__(256) float2 g_cstat[Bb * Hh * CPB];                // per-chunk (m,s), 256 KB
__device__ __align__(256) float g_av_part[(size_t)Bb * Hh * CPB * Dd]; // 8 MB
__device__ __align__(256) float g_out_partial[OCH * Bb * Ff];

static __device__ __forceinline__ float bf16r(float v) {
    return __bfloat162float(__float2bfloat16(v));
}

// Packed bf16 round of two floats (exact expansion via bit ops)
static __device__ __forceinline__ void bf16r2(float a, float b, float& ra, float& rb) {
    __nv_bfloat162 t = __floats2bfloat162_rn(a, b);
    unsigned u = *reinterpret_cast<unsigned*>(&t);
    ra = __uint_as_float(u << 16);
    rb = __uint_as_float(u & 0xffff0000u);
}

// ---------------------------------------------------------------------------
// QKV projection partials
// ---------------------------------------------------------------------------
__global__ __launch_bounds__(256) void proj_partial_kernel(const float* __restrict__ x,
                                                           const float* __restrict__ Wq,
                                                           const float* __restrict__ Wk,
                                                           const float* __restrict__ Wv) {
    int blk = blockIdx.x;
    int p  = blk / FCH;
    int fc = blk - p * FCH;
    const float* W = (p == 0) ? Wq : (p == 1) ? Wk : Wv;
    int tid = threadIdx.x;

    __shared__ float xs[Bb][Ff / FCH];
    for (int i = tid; i < Bb * 32; i += 256) {
        int b = i >> 5, f = i & 31;
        xs[b][f] = x[b * Ff + fc * 32 + f];
    }
    __syncthreads();

    float4 acc[Bb];
#pragma unroll
    for (int b = 0; b < Bb; b++) acc[b] = make_float4(0.f, 0.f, 0.f, 0.f);

    const float4* Wp = (const float4*)(W + (size_t)(fc * 32) * HD) + tid;
#pragma unroll 4
    for (int f = 0; f < 32; f++) {
        float4 w = Wp[(size_t)f * 256];
#pragma unroll
        for (int b = 0; b < Bb; b++) {
            float xv = xs[b][f];
            acc[b].x = fmaf(xv, w.x, acc[b].x);
            acc[b].y = fmaf(xv, w.y, acc[b].y);
            acc[b].z = fmaf(xv, w.z, acc[b].z);
            acc[b].w = fmaf(xv, w.w, acc[b].w);
        }
    }
#pragma unroll
    for (int b = 0; b < Bb; b++)
        ((float4*)(g_proj_partial + ((size_t)(p * FCH + fc) * Bb + b) * HD))[tid] = acc[b];
}

// Reduce proj partials; also writes new_idx output (absorbs old prep kernel)
__global__ void proj_reduce_kernel(const float* __restrict__ bq,
                                   const float* __restrict__ bk,
                                   const float* __restrict__ bv,
                                   const int* __restrict__ kv_idx,
                                   float* __restrict__ out) {
    int i = blockIdx.x * blockDim.x + threadIdx.x;
    if (i < 3 * Bb * HD) {
        int p = i / (Bb * HD);
        int rem = i - p * (Bb * HD);
        int b = rem / HD, o = rem - b * HD;
        float s = ((p == 0) ? bq : (p == 1) ? bk : bv)[o];
#pragma unroll 8
        for (int c = 0; c < FCH; c++)
            s += g_proj_partial[((size_t)(p * FCH + c) * Bb + b) * HD + o];
        g_qkv[i] = s;
    }
    if (blockIdx.x == 0 && threadIdx.x < Bb)
        out[OFF_IDX + threadIdx.x] = (float)(kv_idx[threadIdx.x] + 1);
}

// ---------------------------------------------------------------------------
// Kernel A: fused K copy + insert + logits + per-chunk softmax stats.
// Butterfly multi-reduce identical to R7 (bit-identical numerics).
// After slog writeback, each 16-thread group computes its head's chunk
// (max, sum-of-exp) and stores to g_cstat.
// ---------------------------------------------------------------------------
__global__ __launch_bounds__(256) void copyk_logits_kernel(const float* __restrict__ kvk,
                                                           const int* __restrict__ kv_idx,
                                                           float* __restrict__ out) {
    int blk = blockIdx.x;
    int b = blk >> 7;
    int c = blk & (CPB - 1);
    int l0 = c * ROWS;
    int kvi = kv_idx[b];
    int seq = min(kvi + 1, Ll);
    int idx = kvi & (Ll - 1);
    int tid = threadIdx.x, lane = tid & 31, warp = tid >> 5;
    bool chunk_live = (l0 < seq);

    __shared__ __align__(16) float q_s[HD];
    __shared__ __align__(16) float slog[Hh][ROWS];

    if (chunk_live) {
        for (int i = tid; i < HD; i += 256) q_s[i] = bf16r(g_qkv[(size_t)b * HD + i]);
        __syncthreads();
    }

    const float4* knew4 = (const float4*)(g_qkv + (size_t)Bb * HD + (size_t)b * HD);

    bool s3 = (lane & 8) != 0;
    bool s2 = (lane & 4) != 0;
    bool s1 = (lane & 2) != 0;
    int h_out = 2 * ((lane >> 1) & 7) + (lane >> 4);

#pragma unroll
    for (int t = 0; t < ROWS / 8; t++) {
        int rl = warp + 8 * t;
        int l = l0 + rl;
        const float4* src = (l == idx) ? knew4
                          : (const float4*)(kvk + ((size_t)b * Ll + l) * HD);
        float4* dst = (float4*)(out + OFF_K + ((size_t)b * Ll + l) * HD);
        float4 v[8];
#pragma unroll
        for (int j = 0; j < 8; j++) v[j] = __ldcs(src + j * 32 + lane);
#pragma unroll
        for (int j = 0; j < 8; j++) __stcs(dst + j * 32 + lane, v[j]);
        if (l < seq) {
            float p[8];
#pragma unroll
            for (int j = 0; j < 8; j++) {
                int h = 2 * j + (lane >> 4);
                const float* qh = q_s + h * Dd + (lane & 15) * 4;
                float r0, r1, r2, r3;
                bf16r2(v[j].x, v[j].y, r0, r1);
                bf16r2(v[j].z, v[j].w, r2, r3);
                p[j] = r0 * qh[0] + r1 * qh[1] + r2 * qh[2] + r3 * qh[3];
            }
            float a0[4];
#pragma unroll
            for (int m = 0; m < 4; m++) {
                float send = s3 ? p[m] : p[m + 4];
                float r = __shfl_xor_sync(0xffffffffu, send, 8, 16);
                float keep = s3 ? p[m + 4] : p[m];
                a0[m] = keep + r;
            }
            float b0[2];
#pragma unroll
            for (int m = 0; m < 2; m++) {
                float send = s2 ? a0[m] : a0[m + 2];
                float r = __shfl_xor_sync(0xffffffffu, send, 4, 16);
                float keep = s2 ? a0[m + 2] : a0[m];
                b0[m] = keep + r;
            }
            {
                float send = s1 ? b0[0] : b0[1];
                float r = __shfl_xor_sync(0xffffffffu, send, 2, 16);
                float keep = s1 ? b0[1] : b0[0];
                b0[0] = keep + r;
            }
            b0[0] += __shfl_xor_sync(0xffffffffu, b0[0], 1, 16);
            if ((lane & 1) == 0) slog[h_out][rl] = b0[0] * 0.125f;
        }
    }

    if (chunk_live) {
        __syncthreads();
        int h = tid >> 4, r4 = tid & 15;
        float4 vv = ((const float4*)slog[h])[r4];
        ((float4*)(g_logits + ((size_t)(b * Hh + h)) * Ll + l0))[r4] = vv;

        // Per-chunk stats for head h over this chunk's live rows.
        int lmax = seq - l0;                  // >0; rows >= lmax invalid
        int r = r4 * 4;
        float v0 = (r     < lmax) ? vv.x : -INFINITY;
        float v1 = (r + 1 < lmax) ? vv.y : -INFINITY;
        float v2 = (r + 2 < lmax) ? vv.z : -INFINITY;
        float v3 = (r + 3 < lmax) ? vv.w : -INFINITY;
        float m = fmaxf(fmaxf(v0, v1), fmaxf(v2, v3));
#pragma unroll
        for (int off = 8; off > 0; off >>= 1)
            m = fmaxf(m, __shfl_xor_sync(0xffffffffu, m, off, 16));
        float s = expf(v0 - m) + expf(v1 - m) + expf(v2 - m) + expf(v3 - m);
#pragma unroll
        for (int off = 8; off > 0; off >>= 1)
            s += __shfl_xor_sync(0xffffffffu, s, off, 16);
        if ((lane & 15) == 0)
            g_cstat[(b * Hh + h) * CPB + c] = make_float2(m, s);
    }
}

// ---------------------------------------------------------------------------
// Kernel C: fused V copy + insert + AV partials. Combines chunk stats
// in-block (M = max m_c exactly the global max; S = sum exp(m_c-M)*s_c).
// ---------------------------------------------------------------------------
__global__ __launch_bounds__(256) void copyv_av_kernel(const float* __restrict__ kvv,
                                                       const int* __restrict__ kv_idx,
                                                       float* __restrict__ out) {
    int blk = blockIdx.x;
    int b = blk >> 7;
    int c = blk & (CPB - 1);
    int l0 = c * ROWS;
    int kvi = kv_idx[b];
    int seq = min(kvi + 1, Ll);
    int idx = kvi & (Ll - 1);
    int tid = threadIdx.x, lane = tid & 31, warp = tid >> 5;
    int bh0 = b * Hh;

    __shared__ __align__(16) float prob_s[Hh][ROWS];
    __shared__ __align__(16) float wacc[8][HD];
    __shared__ float sM[Hh], sS[Hh];

    if (l0 >= seq) {
        // Dead chunk: pure streaming copy
#pragma unroll
        for (int t = 0; t < ROWS / 8; t++) {
            int l = l0 + warp + 8 * t;
            const float4* src = (const float4*)(kvv + ((size_t)b * Ll + l) * HD);
            float4* dst = (float4*)(out + OFF_V + ((size_t)b * Ll + l) * HD);
            float4 v[8];
#pragma unroll
            for (int j = 0; j < 8; j++) v[j] = __ldcs(src + j * 32 + lane);
#pragma unroll
            for (int j = 0; j < 8; j++) __stcs(dst + j * 32 + lane, v[j]);
        }
        return;
    }

    // Combine per-chunk stats -> global (M, S) per head (16 threads/head)
    {
        int h = tid >> 4, sub = tid & 15;
        int smax = (seq + ROWS - 1) / ROWS;
        const float2* cs = g_cstat + (bh0 + h) * CPB;
        float m = -INFINITY;
        for (int cc = sub; cc < smax; cc += 16) m = fmaxf(m, cs[cc].x);
#pragma unroll
        for (int off = 8; off > 0; off >>= 1)
            m = fmaxf(m, __shfl_xor_sync(0xffffffffu, m, off, 16));
        float s = 0.0f;
        for (int cc = sub; cc < smax; cc += 16) {
            float2 t = cs[cc];
            s += expf(t.x - m) * t.y;
        }
#pragma unroll
        for (int off = 8; off > 0; off >>= 1)
            s += __shfl_xor_sync(0xffffffffu, s, off, 16);
        if (sub == 0) { sM[h] = m; sS[h] = s; }
    }
    __syncthreads();

    // Stage bf16-rounded probs (0 for rows >= seq)
    {
        int h = tid >> 4, r4 = tid & 15;
        float4 lg4 = ((const float4*)(g_logits + ((size_t)(bh0 + h)) * Ll + l0))[r4];
        float m = sM[h];
        float inv_s = 1.0f / sS[h];
        int r = r4 * 4;
        float4 pv;
        pv.x = (l0 + r     < seq) ? bf16r(expf(lg4.x - m) * inv_s) : 0.0f;
        pv.y = (l0 + r + 1 < seq) ? bf16r(expf(lg4.y - m) * inv_s) : 0.0f;
        pv.z = (l0 + r + 2 < seq) ? bf16r(expf(lg4.z - m) * inv_s) : 0.0f;
        pv.w = (l0 + r + 3 < seq) ? bf16r(expf(lg4.w - m) * inv_s) : 0.0f;
        ((float4*)prob_s[h])[r4] = pv;
    }
    __syncthreads();

    const float4* vnew4 = (const float4*)(g_qkv + (size_t)2 * Bb * HD + (size_t)b * HD);

    float acc[8][4];
#pragma unroll
    for (int j = 0; j < 8; j++)
#pragma unroll
        for (int i = 0; i < 4; i++) acc[j][i] = 0.0f;

#pragma unroll
    for (int t = 0; t < ROWS / 8; t++) {
        int rl = warp + 8 * t;
        int l = l0 + rl;
        const float4* src = (l == idx) ? vnew4
                          : (const float4*)(kvv + ((size_t)b * Ll + l) * HD);
        float4* dst = (float4*)(out + OFF_V + ((size_t)b * Ll + l) * HD);
        float4 v[8];
#pragma unroll
        for (int j = 0; j < 8; j++) v[j] = __ldcs(src + j * 32 + lane);
#pragma unroll
        for (int j = 0; j < 8; j++) __stcs(dst + j * 32 + lane, v[j]);
#pragma unroll
        for (int j = 0; j < 8; j++) {
            int h = 2 * j + (lane >> 4);
            float pb = prob_s[h][rl];
            float r0, r1, r2, r3;
            bf16r2(v[j].x, v[j].y, r0, r1);
            bf16r2(v[j].z, v[j].w, r2, r3);
            acc[j][0] = fmaf(pb, r0, acc[j][0]);
            acc[j][1] = fmaf(pb, r1, acc[j][1]);
            acc[j][2] = fmaf(pb, r2, acc[j][2]);
            acc[j][3] = fmaf(pb, r3, acc[j][3]);
        }
    }

#pragma unroll
    for (int j = 0; j < 8; j++) {
        int h = 2 * j + (lane >> 4);
        int d = (lane & 15) * 4;
#pragma unroll
        for (int i = 0; i < 4; i++)
            wacc[warp][h * Dd + d + i] = acc[j][i];
    }
    __syncthreads();

    for (int i = tid; i < HD; i += 256) {
        float s = 0.0f;
#pragma unroll
        for (int w = 0; w < 8; w++) s += wacc[w][i];
        int h = i >> 6, d = i & 63;
        g_av_part[(((size_t)(bh0 + h)) * CPB + c) * Dd + d] = s;
    }
}

// ---------------------------------------------------------------------------
// Output projection: fuses the av chunk reduce (same chunk order as the old
// av_reduce kernel -> identical numerics) into the attn staging.
// ---------------------------------------------------------------------------
__global__ __launch_bounds__(256) void outproj_partial_kernel(const float* __restrict__ Wo,
                                                              const int* __restrict__ kv_idx) {
    int hc = blockIdx.x;
    int tid = threadIdx.x;

    __shared__ float as[Bb][HD / OCH];
    for (int i = tid; i < Bb * 32; i += 256) {
        int b = i >> 5, j = i & 31;
        int hd = hc * 32 + j;
        int bh = b * Hh + (hd >> 6);
        int d = hd & 63;
        int seq = min(kv_idx[b] + 1, Ll);
        int smax = (seq + ROWS - 1) / ROWS;
        const float* src = g_av_part + (size_t)bh * CPB * Dd + d;
        float t = 0.0f;
#pragma unroll 4
        for (int s = 0; s < smax; s++)
            t += src[(size_t)s * Dd];
        as[b][j] = bf16r(t);
    }
    __syncthreads();

    float4 acc[Bb];
#pragma unroll
    for (int b = 0; b < Bb; b++) acc[b] = make_float4(0.f, 0.f, 0.f, 0.f);

    const float4* Wp = (const float4*)(Wo + (size_t)(hc * 32) * Ff) + tid;
#pragma unroll 4
    for (int j = 0; j < 32; j++) {
        float4 w = Wp[(size_t)j * 256];
#pragma unroll
        for (int b = 0; b < Bb; b++) {
            float av = as[b][j];
            acc[b].x = fmaf(av, w.x, acc[b].x);
            acc[b].y = fmaf(av, w.y, acc[b].y);
            acc[b].z = fmaf(av, w.z, acc[b].z);
            acc[b].w = fmaf(av, w.w, acc[b].w);
        }
    }
#pragma unroll
    for (int b = 0; b < Bb; b++)
        ((float4*)(g_out_partial + ((size_t)hc * Bb + b) * Ff))[tid] = acc[b];
}

__global__ void outproj_reduce_kernel(const float* __restrict__ bo,
                                      float* __restrict__ out) {
    int i = blockIdx.x * blockDim.x + threadIdx.x;
    if (i < Bb * Ff) {
        int f = i & (Ff - 1);
        float s = bo[f];
#pragma unroll 8
        for (int c = 0; c < OCH; c++)
            s += g_out_partial[(size_t)c * Bb * Ff + i];
        out[OFF_Y + i] = s;
    }
}

// ---------------------------------------------------------------------------
extern "C" void kernel_launch(void* const* d_in, const int* in_sizes, int n_in,
                              void* d_out, int out_size) {
    const float* x    = (const float*)d_in[0];
    const float* kvk  = (const float*)d_in[1];
    const float* kvv  = (const float*)d_in[2];
    const int*   kidx = (const int*)  d_in[3];
    const float* Wq   = (const float*)d_in[4];
    const float* bq   = (const float*)d_in[5];
    const float* Wk   = (const float*)d_in[6];
    const float* bk   = (const float*)d_in[7];
    const float* Wv   = (const float*)d_in[8];
    const float* bv   = (const float*)d_in[9];
    const float* Wo   = (const float*)d_in[10];
    const float* bo   = (const float*)d_in[11];
    float* out = (float*)d_out;

    proj_partial_kernel<<<3 * FCH, 256>>>(x, Wq, Wk, Wv);         // 1
    proj_reduce_kernel<<<48, 1024>>>(bq, bk, bv, kidx, out);      // 2
    copyk_logits_kernel<<<Bb * CPB, 256>>>(kvk, kidx, out);       // 3
    copyv_av_kernel<<<Bb * CPB, 256>>>(kvv, kidx, out);           // 4 <- ncu target
    outproj_partial_kernel<<<OCH, 256>>>(Wo, kidx);               // 5
    outproj_reduce_kernel<<<16, 1024>>>(bo, out);                 // 6
}

// round 11
// speedup vs baseline: 3.0147x; 1.0061x over previous
#include <cuda_runtime.h>
#include <cuda_bf16.h>
#include <math.h>

#define Bb 16
#define Ff 1024
#define Hh 16
#define Dd 64
#define Ll 8192
#define HD 1024        // H*D
#define ROWS 64        // rows per chunk in fused copy kernels
#define CPB (Ll / ROWS) // 128 chunks per batch
#define FCH 64         // proj f-chunks (each 16 wide)
#define OCH 64         // outproj hd-chunks (each 16 wide)

// Output layout: y [B,F] | kv_key [B,L,H,D] | kv_value [B,L,H,D] | new_idx [B]
#define KV_ELEMS ((size_t)Bb * Ll * HD)
#define OFF_Y   ((size_t)0)
#define OFF_K   ((size_t)(Bb * Ff))
#define OFF_V   (OFF_K + KV_ELEMS)
#define OFF_IDX (OFF_V + KV_ELEMS)

// Scratch (device globals)
__device__ __align__(256) float g_qkv[3 * Bb * HD];
__device__ __align__(256) float g_proj_partial[3 * FCH * Bb * HD];      // 12 MB (L2-resident)
__device__ __align__(256) float g_logits[(size_t)Bb * Hh * Ll];         // 8 MB
__device__ __align__(256) float2 g_cstat[Bb * Hh * CPB];                // 256 KB
__device__ __align__(256) float g_av_part[(size_t)Bb * Hh * CPB * Dd];  // 8 MB
__device__ __align__(256) float g_out_partial[OCH * Bb * Ff];           // 4 MB (L2-resident)

static __device__ __forceinline__ float bf16r(float v) {
    return __bfloat162float(__float2bfloat16(v));
}

// Packed bf16 round of two floats (exact expansion via bit ops)
static __device__ __forceinline__ void bf16r2(float a, float b, float& ra, float& rb) {
    __nv_bfloat162 t = __floats2bfloat162_rn(a, b);
    unsigned u = *reinterpret_cast<unsigned*>(&t);
    ra = __uint_as_float(u << 16);
    rb = __uint_as_float(u & 0xffff0000u);
}

// ---------------------------------------------------------------------------
// QKV projection partials: 192 blocks = 3 proj x 64 f-chunks (16 wide)
// ---------------------------------------------------------------------------
__global__ __launch_bounds__(256) void proj_partial_kernel(const float* __restrict__ x,
                                                           const float* __restrict__ Wq,
                                                           const float* __restrict__ Wk,
                                                           const float* __restrict__ Wv) {
    int blk = blockIdx.x;
    int p  = blk / FCH;
    int fc = blk - p * FCH;
    const float* W = (p == 0) ? Wq : (p == 1) ? Wk : Wv;
    int tid = threadIdx.x;

    __shared__ float xs[Bb][Ff / FCH];   // 16 x 16
    if (tid < Bb * 16) {
        int b = tid >> 4, f = tid & 15;
        xs[b][f] = x[b * Ff + fc * 16 + f];
    }
    __syncthreads();

    float4 acc[Bb];
#pragma unroll
    for (int b = 0; b < Bb; b++) acc[b] = make_float4(0.f, 0.f, 0.f, 0.f);

    const float4* Wp = (const float4*)(W + (size_t)(fc * 16) * HD) + tid;
#pragma unroll 4
    for (int f = 0; f < 16; f++) {
        float4 w = Wp[(size_t)f * 256];
#pragma unroll
        for (int b = 0; b < Bb; b++) {
            float xv = xs[b][f];
            acc[b].x = fmaf(xv, w.x, acc[b].x);
            acc[b].y = fmaf(xv, w.y, acc[b].y);
            acc[b].z = fmaf(xv, w.z, acc[b].z);
            acc[b].w = fmaf(xv, w.w, acc[b].w);
        }
    }
#pragma unroll
    for (int b = 0; b < Bb; b++)
        ((float4*)(g_proj_partial + ((size_t)(p * FCH + fc) * Bb + b) * HD))[tid] = acc[b];
}

// Reduce proj partials (L2 hits); also writes new_idx output
__global__ __launch_bounds__(256) void proj_reduce_kernel(const float* __restrict__ bq,
                                                          const float* __restrict__ bk,
                                                          const float* __restrict__ bv,
                                                          const int* __restrict__ kv_idx,
                                                          float* __restrict__ out) {
    int i = blockIdx.x * 256 + threadIdx.x;   // < 3*B*HD = 49152
    if (i < 3 * Bb * HD) {
        int p = i / (Bb * HD);
        int rem = i - p * (Bb * HD);
        int b = rem / HD, o = rem - b * HD;
        float s = ((p == 0) ? bq : (p == 1) ? bk : bv)[o];
#pragma unroll 8
        for (int c = 0; c < FCH; c++)
            s += g_proj_partial[((size_t)(p * FCH + c) * Bb + b) * HD + o];
        g_qkv[i] = s;
    }
    if (blockIdx.x == 0 && threadIdx.x < Bb)
        out[OFF_IDX + threadIdx.x] = (float)(kv_idx[threadIdx.x] + 1);
}

// ---------------------------------------------------------------------------
// Kernel A: fused K copy + insert + logits + per-chunk softmax stats.
// (byte-identical math to the proven R8 kernel, 80% DRAM)
// ---------------------------------------------------------------------------
__global__ __launch_bounds__(256) void copyk_logits_kernel(const float* __restrict__ kvk,
                                                           const int* __restrict__ kv_idx,
                                                           float* __restrict__ out) {
    int blk = blockIdx.x;
    int b = blk >> 7;
    int c = blk & (CPB - 1);
    int l0 = c * ROWS;
    int kvi = kv_idx[b];
    int seq = min(kvi + 1, Ll);
    int idx = kvi & (Ll - 1);
    int tid = threadIdx.x, lane = tid & 31, warp = tid >> 5;
    bool chunk_live = (l0 < seq);

    __shared__ __align__(16) float q_s[HD];
    __shared__ __align__(16) float slog[Hh][ROWS];

    if (chunk_live) {
        for (int i = tid; i < HD; i += 256) q_s[i] = bf16r(g_qkv[(size_t)b * HD + i]);
        __syncthreads();
    }

    const float4* knew4 = (const float4*)(g_qkv + (size_t)Bb * HD + (size_t)b * HD);

    bool s3 = (lane & 8) != 0;
    bool s2 = (lane & 4) != 0;
    bool s1 = (lane & 2) != 0;
    int h_out = 2 * ((lane >> 1) & 7) + (lane >> 4);

#pragma unroll
    for (int t = 0; t < ROWS / 8; t++) {
        int rl = warp + 8 * t;
        int l = l0 + rl;
        const float4* src = (l == idx) ? knew4
                          : (const float4*)(kvk + ((size_t)b * Ll + l) * HD);
        float4* dst = (float4*)(out + OFF_K + ((size_t)b * Ll + l) * HD);
        float4 v[8];
#pragma unroll
        for (int j = 0; j < 8; j++) v[j] = __ldcs(src + j * 32 + lane);
#pragma unroll
        for (int j = 0; j < 8; j++) __stcs(dst + j * 32 + lane, v[j]);
        if (l < seq) {
            float p[8];
#pragma unroll
            for (int j = 0; j < 8; j++) {
                int h = 2 * j + (lane >> 4);
                const float* qh = q_s + h * Dd + (lane & 15) * 4;
                float r0, r1, r2, r3;
                bf16r2(v[j].x, v[j].y, r0, r1);
                bf16r2(v[j].z, v[j].w, r2, r3);
                p[j] = r0 * qh[0] + r1 * qh[1] + r2 * qh[2] + r3 * qh[3];
            }
            float a0[4];
#pragma unroll
            for (int m = 0; m < 4; m++) {
                float send = s3 ? p[m] : p[m + 4];
                float r = __shfl_xor_sync(0xffffffffu, send, 8, 16);
                float keep = s3 ? p[m + 4] : p[m];
                a0[m] = keep + r;
            }
            float b0[2];
#pragma unroll
            for (int m = 0; m < 2; m++) {
                float send = s2 ? a0[m] : a0[m + 2];
                float r = __shfl_xor_sync(0xffffffffu, send, 4, 16);
                float keep = s2 ? a0[m + 2] : a0[m];
                b0[m] = keep + r;
            }
            {
                float send = s1 ? b0[0] : b0[1];
                float r = __shfl_xor_sync(0xffffffffu, send, 2, 16);
                float keep = s1 ? b0[1] : b0[0];
                b0[0] = keep + r;
            }
            b0[0] += __shfl_xor_sync(0xffffffffu, b0[0], 1, 16);
            if ((lane & 1) == 0) slog[h_out][rl] = b0[0] * 0.125f;
        }
    }

    if (chunk_live) {
        __syncthreads();
        int h = tid >> 4, r4 = tid & 15;
        float4 vv = ((const float4*)slog[h])[r4];
        ((float4*)(g_logits + ((size_t)(b * Hh + h)) * Ll + l0))[r4] = vv;

        int lmax = seq - l0;
        int r = r4 * 4;
        float v0 = (r     < lmax) ? vv.x : -INFINITY;
        float v1 = (r + 1 < lmax) ? vv.y : -INFINITY;
        float v2 = (r + 2 < lmax) ? vv.z : -INFINITY;
        float v3 = (r + 3 < lmax) ? vv.w : -INFINITY;
        float m = fmaxf(fmaxf(v0, v1), fmaxf(v2, v3));
#pragma unroll
        for (int off = 8; off > 0; off >>= 1)
            m = fmaxf(m, __shfl_xor_sync(0xffffffffu, m, off, 16));
        float s = expf(v0 - m) + expf(v1 - m) + expf(v2 - m) + expf(v3 - m);
#pragma unroll
        for (int off = 8; off > 0; off >>= 1)
            s += __shfl_xor_sync(0xffffffffu, s, off, 16);
        if ((lane & 15) == 0)
            g_cstat[(b * Hh + h) * CPB + c] = make_float2(m, s);
    }
}

// ---------------------------------------------------------------------------
// Kernel C: fused V copy + insert + AV partials (byte-identical to proven R8)
// ---------------------------------------------------------------------------
__global__ __launch_bounds__(256) void copyv_av_kernel(const float* __restrict__ kvv,
                                                       const int* __restrict__ kv_idx,
                                                       float* __restrict__ out) {
    int blk = blockIdx.x;
    int b = blk >> 7;
    int c = blk & (CPB - 1);
    int l0 = c * ROWS;
    int kvi = kv_idx[b];
    int seq = min(kvi + 1, Ll);
    int idx = kvi & (Ll - 1);
    int tid = threadIdx.x, lane = tid & 31, warp = tid >> 5;
    int bh0 = b * Hh;

    __shared__ __align__(16) float prob_s[Hh][ROWS];
    __shared__ __align__(16) float wacc[8][HD];
    __shared__ float sM[Hh], sS[Hh];

    if (l0 >= seq) {
#pragma unroll
        for (int t = 0; t < ROWS / 8; t++) {
            int l = l0 + warp + 8 * t;
            const float4* src = (const float4*)(kvv + ((size_t)b * Ll + l) * HD);
            float4* dst = (float4*)(out + OFF_V + ((size_t)b * Ll + l) * HD);
            float4 v[8];
#pragma unroll
            for (int j = 0; j < 8; j++) v[j] = __ldcs(src + j * 32 + lane);
#pragma unroll
            for (int j = 0; j < 8; j++) __stcs(dst + j * 32 + lane, v[j]);
        }
        return;
    }

    {
        int h = tid >> 4, sub = tid & 15;
        int smax = (seq + ROWS - 1) / ROWS;
        const float2* cs = g_cstat + (bh0 + h) * CPB;
        float m = -INFINITY;
        for (int cc = sub; cc < smax; cc += 16) m = fmaxf(m, cs[cc].x);
#pragma unroll
        for (int off = 8; off > 0; off >>= 1)
            m = fmaxf(m, __shfl_xor_sync(0xffffffffu, m, off, 16));
        float s = 0.0f;
        for (int cc = sub; cc < smax; cc += 16) {
            float2 t = cs[cc];
            s += expf(t.x - m) * t.y;
        }
#pragma unroll
        for (int off = 8; off > 0; off >>= 1)
            s += __shfl_xor_sync(0xffffffffu, s, off, 16);
        if (sub == 0) { sM[h] = m; sS[h] = s; }
    }
    __syncthreads();

    {
        int h = tid >> 4, r4 = tid & 15;
        float4 lg4 = ((const float4*)(g_logits + ((size_t)(bh0 + h)) * Ll + l0))[r4];
        float m = sM[h];
        float inv_s = 1.0f / sS[h];
        int r = r4 * 4;
        float4 pv;
        pv.x = (l0 + r     < seq) ? bf16r(expf(lg4.x - m) * inv_s) : 0.0f;
        pv.y = (l0 + r + 1 < seq) ? bf16r(expf(lg4.y - m) * inv_s) : 0.0f;
        pv.z = (l0 + r + 2 < seq) ? bf16r(expf(lg4.z - m) * inv_s) : 0.0f;
        pv.w = (l0 + r + 3 < seq) ? bf16r(expf(lg4.w - m) * inv_s) : 0.0f;
        ((float4*)prob_s[h])[r4] = pv;
    }
    __syncthreads();

    const float4* vnew4 = (const float4*)(g_qkv + (size_t)2 * Bb * HD + (size_t)b * HD);

    float acc[8][4];
#pragma unroll
    for (int j = 0; j < 8; j++)
#pragma unroll
        for (int i = 0; i < 4; i++) acc[j][i] = 0.0f;

#pragma unroll
    for (int t = 0; t < ROWS / 8; t++) {
        int rl = warp + 8 * t;
        int l = l0 + rl;
        const float4* src = (l == idx) ? vnew4
                          : (const float4*)(kvv + ((size_t)b * Ll + l) * HD);
        float4* dst = (float4*)(out + OFF_V + ((size_t)b * Ll + l) * HD);
        float4 v[8];
#pragma unroll
        for (int j = 0; j < 8; j++) v[j] = __ldcs(src + j * 32 + lane);
#pragma unroll
        for (int j = 0; j < 8; j++) __stcs(dst + j * 32 + lane, v[j]);
#pragma unroll
        for (int j = 0; j < 8; j++) {
            int h = 2 * j + (lane >> 4);
            float pb = prob_s[h][rl];
            float r0, r1, r2, r3;
            bf16r2(v[j].x, v[j].y, r0, r1);
            bf16r2(v[j].z, v[j].w, r2, r3);
            acc[j][0] = fmaf(pb, r0, acc[j][0]);
            acc[j][1] = fmaf(pb, r1, acc[j][1]);
            acc[j][2] = fmaf(pb, r2, acc[j][2]);
            acc[j][3] = fmaf(pb, r3, acc[j][3]);
        }
    }

#pragma unroll
    for (int j = 0; j < 8; j++) {
        int h = 2 * j + (lane >> 4);
        int d = (lane & 15) * 4;
#pragma unroll
        for (int i = 0; i < 4; i++)
            wacc[warp][h * Dd + d + i] = acc[j][i];
    }
    __syncthreads();

    for (int i = tid; i < HD; i += 256) {
        float s = 0.0f;
#pragma unroll
        for (int w = 0; w < 8; w++) s += wacc[w][i];
        int h = i >> 6, d = i & 63;
        g_av_part[(((size_t)(bh0 + h)) * CPB + c) * Dd + d] = s;
    }
}

// ---------------------------------------------------------------------------
// Output projection: 64 blocks (hd-chunks of 16); av chunk-reduce fused into
// staging (identical s=0..smax order -> identical numerics).
// ---------------------------------------------------------------------------
__global__ __launch_bounds__(256) void outproj_partial_kernel(const float* __restrict__ Wo,
                                                              const int* __restrict__ kv_idx) {
    int hc = blockIdx.x;      // 0..63, chunk of 16 hd
    int tid = threadIdx.x;

    __shared__ float as[Bb][HD / OCH];   // 16 x 16
    if (tid < Bb * 16) {
        int b = tid >> 4, j = tid & 15;
        int hd = hc * 16 + j;
        int bh = b * Hh + (hd >> 6);
        int d = hd & 63;
        int seq = min(kv_idx[b] + 1, Ll);
        int smax = (seq + ROWS - 1) / ROWS;
        const float* src = g_av_part + (size_t)bh * CPB * Dd + d;
        float t = 0.0f;
#pragma unroll 4
        for (int s = 0; s < smax; s++)
            t += src[(size_t)s * Dd];
        as[b][j] = bf16r(t);
    }
    __syncthreads();

    float4 acc[Bb];
#pragma unroll
    for (int b = 0; b < Bb; b++) acc[b] = make_float4(0.f, 0.f, 0.f, 0.f);

    const float4* Wp = (const float4*)(Wo + (size_t)(hc * 16) * Ff) + tid;
#pragma unroll 4
    for (int j = 0; j < 16; j++) {
        float4 w = Wp[(size_t)j * 256];
#pragma unroll
        for (int b = 0; b < Bb; b++) {
            float av = as[b][j];
            acc[b].x = fmaf(av, w.x, acc[b].x);
            acc[b].y = fmaf(av, w.y, acc[b].y);
            acc[b].z = fmaf(av, w.z, acc[b].z);
            acc[b].w = fmaf(av, w.w, acc[b].w);
        }
    }
#pragma unroll
    for (int b = 0; b < Bb; b++)
        ((float4*)(g_out_partial + ((size_t)hc * Bb + b) * Ff))[tid] = acc[b];
}

__global__ __launch_bounds__(256) void outproj_reduce_kernel(const float* __restrict__ bo,
                                                             float* __restrict__ out) {
    int i = blockIdx.x * 256 + threadIdx.x;   // < B*F = 16384
    if (i < Bb * Ff) {
        int f = i & (Ff - 1);
        float s = bo[f];
#pragma unroll 8
        for (int c = 0; c < OCH; c++)
            s += g_out_partial[(size_t)c * Bb * Ff + i];
        out[OFF_Y + i] = s;
    }
}

// ---------------------------------------------------------------------------
extern "C" void kernel_launch(void* const* d_in, const int* in_sizes, int n_in,
                              void* d_out, int out_size) {
    const float* x    = (const float*)d_in[0];
    const float* kvk  = (const float*)d_in[1];
    const float* kvv  = (const float*)d_in[2];
    const int*   kidx = (const int*)  d_in[3];
    const float* Wq   = (const float*)d_in[4];
    const float* bq   = (const float*)d_in[5];
    const float* Wk   = (const float*)d_in[6];
    const float* bk   = (const float*)d_in[7];
    const float* Wv   = (const float*)d_in[8];
    const float* bv   = (const float*)d_in[9];
    const float* Wo   = (const float*)d_in[10];
    const float* bo   = (const float*)d_in[11];
    float* out = (float*)d_out;

    proj_partial_kernel<<<3 * FCH, 256>>>(x, Wq, Wk, Wv);         // 1 (192 blocks)
    proj_reduce_kernel<<<192, 256>>>(bq, bk, bv, kidx, out);      // 2
    copyk_logits_kernel<<<Bb * CPB, 256>>>(kvk, kidx, out);       // 3
    copyv_av_kernel<<<Bb * CPB, 256>>>(kvv, kidx, out);           // 4 <- ncu target
    outproj_partial_kernel<<<OCH, 256>>>(Wo, kidx);               // 5 (64 blocks)
    outproj_reduce_kernel<<<64, 256>>>(bo, out);                  // 6
}